// round 1
// baseline (speedup 1.0000x reference)
#include <cuda_runtime.h>
#include <math.h>

#define SEQ 2048
#define HID 2048
#define KVD 512
#define NQH 32
#define NKH 8

// Scratch (no allocations allowed)
__device__ float g_Q[SEQ * HID];
__device__ float g_K[SEQ * KVD];
__device__ float g_V[SEQ * KVD];
__device__ float g_O[SEQ * HID];

// ---------------------------------------------------------------------------
// SGEMM: C[M,N] = A[M,K] @ B[K,N], all row-major fp32.
// 128x128 block tile, BK=8, 256 threads, 8x8 register micro-tile with
// split-half (4+4) layout for conflict-free float4 smem reads.
// ---------------------------------------------------------------------------
__global__ __launch_bounds__(256) void sgemm128(
    const float* __restrict__ A, const float* __restrict__ B,
    float* __restrict__ C, int M, int N, int K) {
    __shared__ float As[8][128];  // transposed: As[k][m]
    __shared__ float Bs[8][128];

    const int tid = threadIdx.x;
    const int tx = tid & 15;        // 0..15 -> N dim
    const int ty = tid >> 4;        // 0..15 -> M dim
    const int rowBase = blockIdx.y * 128;
    const int colBase = blockIdx.x * 128;

    const int aRow = tid >> 1;            // 0..127
    const int aCol = (tid & 1) * 4;       // 0 or 4
    const int bRow = tid >> 5;            // 0..7
    const int bCol = (tid & 31) * 4;      // 0..124

    const float* Aptr = A + (size_t)(rowBase + aRow) * K + aCol;
    const float* Bptr = B + (size_t)bRow * N + colBase + bCol;

    float acc[8][8];
#pragma unroll
    for (int i = 0; i < 8; i++)
#pragma unroll
        for (int j = 0; j < 8; j++) acc[i][j] = 0.f;

    for (int k0 = 0; k0 < K; k0 += 8) {
        float4 av = *(const float4*)(Aptr + k0);
        float4 bv = *(const float4*)(Bptr + (size_t)k0 * N);
        As[aCol + 0][aRow] = av.x;
        As[aCol + 1][aRow] = av.y;
        As[aCol + 2][aRow] = av.z;
        As[aCol + 3][aRow] = av.w;
        *(float4*)&Bs[bRow][bCol] = bv;
        __syncthreads();

#pragma unroll
        for (int k = 0; k < 8; k++) {
            float4 a0 = *(const float4*)&As[k][ty * 4];
            float4 a1 = *(const float4*)&As[k][ty * 4 + 64];
            float4 b0 = *(const float4*)&Bs[k][tx * 4];
            float4 b1 = *(const float4*)&Bs[k][tx * 4 + 64];
            float a[8] = {a0.x, a0.y, a0.z, a0.w, a1.x, a1.y, a1.z, a1.w};
            float b[8] = {b0.x, b0.y, b0.z, b0.w, b1.x, b1.y, b1.z, b1.w};
#pragma unroll
            for (int i = 0; i < 8; i++)
#pragma unroll
                for (int j = 0; j < 8; j++) acc[i][j] = fmaf(a[i], b[j], acc[i][j]);
        }
        __syncthreads();
    }

#pragma unroll
    for (int ih = 0; ih < 2; ih++)
#pragma unroll
        for (int ii = 0; ii < 4; ii++) {
            int r = rowBase + ih * 64 + ty * 4 + ii;
#pragma unroll
            for (int jh = 0; jh < 2; jh++) {
                float4 v = make_float4(acc[ih * 4 + ii][jh * 4 + 0],
                                       acc[ih * 4 + ii][jh * 4 + 1],
                                       acc[ih * 4 + ii][jh * 4 + 2],
                                       acc[ih * 4 + ii][jh * 4 + 3]);
                *(float4*)&C[(size_t)r * N + colBase + jh * 64 + tx * 4] = v;
            }
        }
}

// ---------------------------------------------------------------------------
// RoPE (nonstandard): half = x[0:32], odd = x[32:64]
// out[0:32] = half*cos + odd*sin ; out[32:64] = half*sin - odd*cos
// angle = (float)pos * inv_freq[j]  (matches reference fp32 computation)
// ---------------------------------------------------------------------------
__global__ void rope_kernel(float* __restrict__ X, const float* __restrict__ inv_freq,
                            int heads) {
    int s = blockIdx.x;
    int h = blockIdx.y;
    int j = threadIdx.x;  // 0..31
    float* p = X + (size_t)s * heads * 64 + h * 64;
    float angle = (float)s * inv_freq[j];
    float sn = sinf(angle), cs = cosf(angle);
    float a = p[j], b = p[32 + j];
    p[j] = a * cs + b * sn;
    p[32 + j] = a * sn - b * cs;
}

// ---------------------------------------------------------------------------
// Flash attention, causal, GQA (q-head qh uses kv-head qh>>2).
// 64x64 tiles, 256 threads (16x16), 4x4 register tile per thread.
// ---------------------------------------------------------------------------
#define FPAD 65
__global__ __launch_bounds__(256) void flash_attn(
    const float* __restrict__ Q, const float* __restrict__ K,
    const float* __restrict__ V, float* __restrict__ O) {
    extern __shared__ float sm[];
    float* Qs = sm;                 // 64*65
    float* Ks = Qs + 64 * FPAD;     // 64*65
    float* Vs = Ks + 64 * FPAD;     // 64*65
    float* Ps = Vs + 64 * FPAD;     // 64*65
    float* red = Ps + 64 * FPAD;    // 64*16
    float* m_s = red + 64 * 16;     // 64
    float* l_s = m_s + 64;          // 64
    float* al_s = l_s + 64;         // 64

    const int tid = threadIdx.x;
    const int tx = tid & 15;
    const int ty = tid >> 4;
    const int ib = blockIdx.x;   // query tile
    const int qh = blockIdx.y;   // query head
    const int kh = qh >> 2;      // kv head
    const float scale = 0.125f;  // 1/sqrt(64)

    const int row0 = ty * 4;
    const int col0 = tx * 4;

    // Load Q tile [64 rows x 64 dims]
    for (int idx = tid; idx < 4096; idx += 256) {
        int r = idx >> 6, c = idx & 63;
        Qs[r * FPAD + c] = Q[(size_t)(ib * 64 + r) * HID + qh * 64 + c];
    }
    if (tid < 64) { m_s[tid] = -1e30f; l_s[tid] = 0.f; }

    float acc[4][4];
#pragma unroll
    for (int i = 0; i < 4; i++)
#pragma unroll
        for (int j = 0; j < 4; j++) acc[i][j] = 0.f;

    for (int jb = 0; jb <= ib; jb++) {
        __syncthreads();  // protect K/V/P reuse + Q/m/l init on first iter
        for (int idx = tid; idx < 4096; idx += 256) {
            int r = idx >> 6, c = idx & 63;
            size_t g = (size_t)(jb * 64 + r) * KVD + kh * 64 + c;
            Ks[r * FPAD + c] = K[g];
            Vs[r * FPAD + c] = V[g];
        }
        __syncthreads();

        // S = Q @ K^T (4x4 per thread)
        float s[4][4];
#pragma unroll
        for (int i = 0; i < 4; i++)
#pragma unroll
            for (int j = 0; j < 4; j++) s[i][j] = 0.f;
#pragma unroll 8
        for (int k = 0; k < 64; k++) {
            float qv[4], kv[4];
#pragma unroll
            for (int i = 0; i < 4; i++) qv[i] = Qs[(row0 + i) * FPAD + k];
#pragma unroll
            for (int j = 0; j < 4; j++) kv[j] = Ks[(col0 + j) * FPAD + k];
#pragma unroll
            for (int i = 0; i < 4; i++)
#pragma unroll
                for (int j = 0; j < 4; j++) s[i][j] = fmaf(qv[i], kv[j], s[i][j]);
        }

        const bool diag = (jb == ib);
#pragma unroll
        for (int i = 0; i < 4; i++)
#pragma unroll
            for (int j = 0; j < 4; j++) {
                s[i][j] *= scale;
                if (diag && (col0 + j) > (row0 + i)) s[i][j] = -1e30f;
            }

        // Row max partials
#pragma unroll
        for (int i = 0; i < 4; i++) {
            float mx = fmaxf(fmaxf(s[i][0], s[i][1]), fmaxf(s[i][2], s[i][3]));
            red[(row0 + i) * 16 + tx] = mx;
        }
        __syncthreads();
        if (tid < 64) {
            float mx = red[tid * 16];
#pragma unroll
            for (int t = 1; t < 16; t++) mx = fmaxf(mx, red[tid * 16 + t]);
            float mold = m_s[tid];
            float mnew = fmaxf(mold, mx);
            al_s[tid] = __expf(mold - mnew);
            m_s[tid] = mnew;
        }
        __syncthreads();

        // P = exp(S - m), partial row sums, rescale accumulator
#pragma unroll
        for (int i = 0; i < 4; i++) {
            float mrow = m_s[row0 + i];
            float al = al_s[row0 + i];
            float rs = 0.f;
#pragma unroll
            for (int j = 0; j < 4; j++) {
                float p = __expf(s[i][j] - mrow);
                Ps[(row0 + i) * FPAD + col0 + j] = p;
                rs += p;
            }
            red[(row0 + i) * 16 + tx] = rs;
#pragma unroll
            for (int j = 0; j < 4; j++) acc[i][j] *= al;
        }
        __syncthreads();
        if (tid < 64) {
            float ssum = 0.f;
#pragma unroll
            for (int t = 0; t < 16; t++) ssum += red[tid * 16 + t];
            l_s[tid] = l_s[tid] * al_s[tid] + ssum;
        }

        // acc += P @ V  (P synced above; l_s write races nothing we read here)
#pragma unroll 8
        for (int j = 0; j < 64; j++) {
            float pv[4], vv[4];
#pragma unroll
            for (int i = 0; i < 4; i++) pv[i] = Ps[(row0 + i) * FPAD + j];
#pragma unroll
            for (int c = 0; c < 4; c++) vv[c] = Vs[j * FPAD + col0 + c];
#pragma unroll
            for (int i = 0; i < 4; i++)
#pragma unroll
                for (int c = 0; c < 4; c++) acc[i][c] = fmaf(pv[i], vv[c], acc[i][c]);
        }
    }
    __syncthreads();  // l_s final values visible

#pragma unroll
    for (int i = 0; i < 4; i++) {
        float inv_l = 1.0f / l_s[row0 + i];
#pragma unroll
        for (int c = 0; c < 4; c++) {
            O[(size_t)(ib * 64 + row0 + i) * HID + qh * 64 + col0 + c] = acc[i][c] * inv_l;
        }
    }
}

// ---------------------------------------------------------------------------
extern "C" void kernel_launch(void* const* d_in, const int* in_sizes, int n_in,
                              void* d_out, int out_size) {
    const float* x        = (const float*)d_in[0];
    const float* q_proj   = (const float*)d_in[1];
    const float* k_proj   = (const float*)d_in[2];
    const float* v_proj   = (const float*)d_in[3];
    const float* o_proj   = (const float*)d_in[4];
    const float* inv_freq = (const float*)d_in[5];
    float* out = (float*)d_out;

    float *Qb, *Kb, *Vb, *Ob;
    cudaGetSymbolAddress((void**)&Qb, g_Q);
    cudaGetSymbolAddress((void**)&Kb, g_K);
    cudaGetSymbolAddress((void**)&Vb, g_V);
    cudaGetSymbolAddress((void**)&Ob, g_O);

    // QKV projections
    sgemm128<<<dim3(HID / 128, SEQ / 128), 256>>>(x, q_proj, Qb, SEQ, HID, HID);
    sgemm128<<<dim3(KVD / 128, SEQ / 128), 256>>>(x, k_proj, Kb, SEQ, KVD, HID);
    sgemm128<<<dim3(KVD / 128, SEQ / 128), 256>>>(x, v_proj, Vb, SEQ, KVD, HID);

    // RoPE on Q (32 heads) and K (8 heads)
    rope_kernel<<<dim3(SEQ, NQH), 32>>>(Qb, inv_freq, NQH);
    rope_kernel<<<dim3(SEQ, NKH), 32>>>(Kb, inv_freq, NKH);

    // Flash attention
    const int smem = (4 * 64 * FPAD + 64 * 16 + 3 * 64) * sizeof(float);
    cudaFuncSetAttribute(flash_attn, cudaFuncAttributeMaxDynamicSharedMemorySize, smem);
    flash_attn<<<dim3(SEQ / 64, NQH), 256, smem>>>(Qb, Kb, Vb, Ob);

    // Output projection
    sgemm128<<<dim3(HID / 128, SEQ / 128), 256>>>(Ob, o_proj, out, SEQ, HID, HID);
}

// round 3
// speedup vs baseline: 1.7327x; 1.7327x over previous
#include <cuda_runtime.h>
#include <cuda_bf16.h>
#include <math.h>
#include <cstdint>

#define SEQ 2048
#define HID 2048
#define KVD 512
#define NQH 32
#define NKH 8

// ---------------- scratch (no allocations allowed) ----------------
__device__ float g_Q[SEQ * HID];
__device__ float g_K[SEQ * KVD];
__device__ float g_V[SEQ * KVD];
__device__ float g_O[SEQ * HID];
__device__ __nv_bfloat16 g_Ahi[SEQ * HID];
__device__ __nv_bfloat16 g_Alo[SEQ * HID];
__device__ __nv_bfloat16 g_Whi[HID * HID];   // transposed weights [N,K]
__device__ __nv_bfloat16 g_Wlo[HID * HID];

// ---------------- helpers ----------------
__device__ __forceinline__ uint32_t smem_u32(const void* p) {
    uint32_t a;
    asm("{ .reg .u64 t; cvta.to.shared.u64 t, %1; cvt.u32.u64 %0, t; }" : "=r"(a) : "l"(p));
    return a;
}

#define LDSM4(r0, r1, r2, r3, addr) \
    asm volatile("ldmatrix.sync.aligned.m8n8.x4.shared.b16 {%0,%1,%2,%3}, [%4];" \
        : "=r"(r0), "=r"(r1), "=r"(r2), "=r"(r3) : "r"(addr))

#define MMA16816(d, a, b0, b1) \
    asm volatile("mma.sync.aligned.m16n8k16.row.col.f32.bf16.bf16.f32 " \
        "{%0,%1,%2,%3},{%4,%5,%6,%7},{%8,%9},{%0,%1,%2,%3};" \
        : "+f"((d)[0]), "+f"((d)[1]), "+f"((d)[2]), "+f"((d)[3]) \
        : "r"((a)[0]), "r"((a)[1]), "r"((a)[2]), "r"((a)[3]), "r"(b0), "r"(b1))

#define CP_ASYNC16(dst, src) \
    asm volatile("cp.async.cg.shared.global [%0], [%1], 16;" :: "r"(dst), "l"(src))
#define CP_COMMIT() asm volatile("cp.async.commit_group;" ::: "memory")
#define CP_WAIT0()  asm volatile("cp.async.wait_group 0;" ::: "memory")

// ---------------- split-convert kernels ----------------
__device__ __forceinline__ uint32_t pack_bf2(__nv_bfloat16 a, __nv_bfloat16 b) {
    __nv_bfloat162 t(a, b);
    return *reinterpret_cast<uint32_t*>(&t);
}

// elementwise: fp32 -> (hi, lo) bf16
__global__ __launch_bounds__(256) void convert_hl(const float* __restrict__ X,
                                                  __nv_bfloat16* __restrict__ hi,
                                                  __nv_bfloat16* __restrict__ lo) {
    int i = blockIdx.x * 256 + threadIdx.x;
    float4 v = *(const float4*)(X + (size_t)i * 4);
    __nv_bfloat16 h0 = __float2bfloat16_rn(v.x), h1 = __float2bfloat16_rn(v.y);
    __nv_bfloat16 h2 = __float2bfloat16_rn(v.z), h3 = __float2bfloat16_rn(v.w);
    __nv_bfloat16 l0 = __float2bfloat16_rn(v.x - __bfloat162float(h0));
    __nv_bfloat16 l1 = __float2bfloat16_rn(v.y - __bfloat162float(h1));
    __nv_bfloat16 l2 = __float2bfloat16_rn(v.z - __bfloat162float(h2));
    __nv_bfloat16 l3 = __float2bfloat16_rn(v.w - __bfloat162float(h3));
    *(uint2*)(hi + (size_t)i * 4) = make_uint2(pack_bf2(h0, h1), pack_bf2(h2, h3));
    *(uint2*)(lo + (size_t)i * 4) = make_uint2(pack_bf2(l0, l1), pack_bf2(l2, l3));
}

// W [K,N] fp32 -> Wt hi/lo [N,K] bf16 (32x32 tiled transpose)
__global__ __launch_bounds__(256) void transpose_hl(const float* __restrict__ W,
                                                    __nv_bfloat16* __restrict__ thi,
                                                    __nv_bfloat16* __restrict__ tlo,
                                                    int K, int N) {
    __shared__ float t[32][33];
    int tx = threadIdx.x & 31, ty = threadIdx.x >> 5;  // ty 0..7
    int k0 = blockIdx.y * 32, n0 = blockIdx.x * 32;
#pragma unroll
    for (int i = 0; i < 4; i++)
        t[ty + i * 8][tx] = W[(size_t)(k0 + ty + i * 8) * N + n0 + tx];
    __syncthreads();
#pragma unroll
    for (int i = 0; i < 4; i++) {
        float v = t[tx][ty + i * 8];
        __nv_bfloat16 h = __float2bfloat16_rn(v);
        __nv_bfloat16 l = __float2bfloat16_rn(v - __bfloat162float(h));
        size_t o = (size_t)(n0 + ty + i * 8) * K + k0 + tx;
        thi[o] = h;
        tlo[o] = l;
    }
}

// ---------------- mma.sync GEMM: C[M,N] = A[M,K] @ Wt[N,K]^T ----------------
// 128x128 block tile, BK=32, 8 warps (2x4), warp tile 64x32.
// Smem tile: 128 rows x 32 bf16, rows padded to 40 bf16 (80B) -> conflict-free ldmatrix.
// Sub-tiles per buffer: Ahi(0) Alo(10240) Bhi(20480) Blo(30720); 2 buffers.
#define TILE_B 10240
#define BUF_B  40960
#define G_SMEM (2 * BUF_B)

__device__ __forceinline__ void tile_async(uint32_t dst, const __nv_bfloat16* src,
                                           int ldk, int tid) {
#pragma unroll
    for (int t = 0; t < 2; t++) {
        int i = tid + t * 256;
        int r = i >> 2, q = i & 3;
        const void* g = src + (size_t)r * ldk + q * 8;
        CP_ASYNC16(dst + r * 80 + q * 16, g);
    }
}

__global__ __launch_bounds__(256, 1) void gemm_mma(
    const __nv_bfloat16* __restrict__ Ahi, const __nv_bfloat16* __restrict__ Alo,
    const __nv_bfloat16* __restrict__ Bhi, const __nv_bfloat16* __restrict__ Blo,
    float* __restrict__ C, int M, int N, int K) {
    extern __shared__ char smem[];
    const uint32_t sb = smem_u32(smem);
    const int tid = threadIdx.x;
    const int w = tid >> 5;
    const int lane = tid & 31;
    const int wm = (w & 1) * 64;       // warp M offset in block
    const int wn = (w >> 1) * 32;      // warp N offset
    const int m0 = blockIdx.y * 128;
    const int n0 = blockIdx.x * 128;

    // ldmatrix lane address components
    const int a_row = lane & 15;             // row within 16
    const int a_kh = (lane >> 4) & 1;        // k half (+8)
    const int b_n = (lane & 7) + ((lane >> 4) << 3);  // n within 16
    const int b_kh = (lane >> 3) & 1;        // k half (+8)

    float acc[4][4][4];
#pragma unroll
    for (int i = 0; i < 4; i++)
#pragma unroll
        for (int j = 0; j < 4; j++)
#pragma unroll
            for (int r = 0; r < 4; r++) acc[i][j][r] = 0.f;

    const int NC = K >> 5;  // chunks of 32

    // prefetch chunk 0 -> buffer 0
    {
        const size_t ak = (size_t)m0 * K;
        const size_t bk = (size_t)n0 * K;
        tile_async(sb,              Ahi + ak, K, tid);
        tile_async(sb + TILE_B,     Alo + ak, K, tid);
        tile_async(sb + 2 * TILE_B, Bhi + bk, K, tid);
        tile_async(sb + 3 * TILE_B, Blo + bk, K, tid);
        CP_COMMIT();
    }

    for (int c = 0; c < NC; c++) {
        CP_WAIT0();
        __syncthreads();
        if (c + 1 < NC) {
            const uint32_t nb = sb + ((c + 1) & 1) * BUF_B;
            const size_t ak = (size_t)m0 * K + (size_t)(c + 1) * 32;
            const size_t bk = (size_t)n0 * K + (size_t)(c + 1) * 32;
            tile_async(nb,              Ahi + ak, K, tid);
            tile_async(nb + TILE_B,     Alo + ak, K, tid);
            tile_async(nb + 2 * TILE_B, Bhi + bk, K, tid);
            tile_async(nb + 3 * TILE_B, Blo + bk, K, tid);
            CP_COMMIT();
        }
        const uint32_t base = sb + (c & 1) * BUF_B;

#pragma unroll
        for (int ks = 0; ks < 32; ks += 16) {
            uint32_t ah[4][4], al[4][4], bh[2][4], bl[2][4];
            const uint32_t aoff = (uint32_t)((wm + a_row) * 80 + (ks + a_kh * 8) * 2);
            const uint32_t boff = (uint32_t)((wn + b_n) * 80 + (ks + b_kh * 8) * 2);
#pragma unroll
            for (int mt = 0; mt < 4; mt++) {
                LDSM4(ah[mt][0], ah[mt][1], ah[mt][2], ah[mt][3],
                      base + aoff + mt * 16 * 80);
                LDSM4(al[mt][0], al[mt][1], al[mt][2], al[mt][3],
                      base + TILE_B + aoff + mt * 16 * 80);
            }
#pragma unroll
            for (int np = 0; np < 2; np++) {
                LDSM4(bh[np][0], bh[np][1], bh[np][2], bh[np][3],
                      base + 2 * TILE_B + boff + np * 16 * 80);
                LDSM4(bl[np][0], bl[np][1], bl[np][2], bl[np][3],
                      base + 3 * TILE_B + boff + np * 16 * 80);
            }
#pragma unroll
            for (int mt = 0; mt < 4; mt++)
#pragma unroll
                for (int np = 0; np < 2; np++) {
                    // hi*hi
                    MMA16816(acc[mt][np * 2 + 0], ah[mt], bh[np][0], bh[np][1]);
                    MMA16816(acc[mt][np * 2 + 1], ah[mt], bh[np][2], bh[np][3]);
                    // hi*lo
                    MMA16816(acc[mt][np * 2 + 0], ah[mt], bl[np][0], bl[np][1]);
                    MMA16816(acc[mt][np * 2 + 1], ah[mt], bl[np][2], bl[np][3]);
                    // lo*hi
                    MMA16816(acc[mt][np * 2 + 0], al[mt], bh[np][0], bh[np][1]);
                    MMA16816(acc[mt][np * 2 + 1], al[mt], bh[np][2], bh[np][3]);
                }
        }
    }

    // epilogue
    const int g = lane >> 2, c2 = lane & 3;
#pragma unroll
    for (int mt = 0; mt < 4; mt++) {
        const int row = m0 + wm + mt * 16 + g;
#pragma unroll
        for (int nt = 0; nt < 4; nt++) {
            const int col = n0 + wn + nt * 8 + c2 * 2;
            *(float2*)&C[(size_t)row * N + col] =
                make_float2(acc[mt][nt][0], acc[mt][nt][1]);
            *(float2*)&C[(size_t)(row + 8) * N + col] =
                make_float2(acc[mt][nt][2], acc[mt][nt][3]);
        }
    }
}

// ---------------- RoPE (warp per (s,h)) ----------------
__global__ __launch_bounds__(256) void rope_kernel(float* __restrict__ X,
                                                   const float* __restrict__ inv_freq, int heads) {
    int idx = blockIdx.x * 8 + (threadIdx.x >> 5);
    int j = threadIdx.x & 31;
    int s = idx / heads;
    int h = idx - s * heads;
    float* p = X + (size_t)s * heads * 64 + h * 64;
    float angle = (float)s * inv_freq[j];
    float sn = sinf(angle), cs = cosf(angle);
    float a = p[j], b = p[32 + j];
    p[j] = a * cs + b * sn;
    p[32 + j] = a * sn - b * cs;
}

// ---------------- flash attention (unchanged, passing) ----------------
#define FPAD 65
__global__ __launch_bounds__(256) void flash_attn(
    const float* __restrict__ Q, const float* __restrict__ K,
    const float* __restrict__ V, float* __restrict__ O) {
    extern __shared__ float sm[];
    float* Qs = sm;
    float* Ks = Qs + 64 * FPAD;
    float* Vs = Ks + 64 * FPAD;
    float* Ps = Vs + 64 * FPAD;
    float* red = Ps + 64 * FPAD;
    float* m_s = red + 64 * 16;
    float* l_s = m_s + 64;
    float* al_s = l_s + 64;

    const int tid = threadIdx.x;
    const int tx = tid & 15;
    const int ty = tid >> 4;
    const int ib = blockIdx.x;
    const int qh = blockIdx.y;
    const int kh = qh >> 2;
    const float scale = 0.125f;
    const int row0 = ty * 4;
    const int col0 = tx * 4;

    for (int idx = tid; idx < 4096; idx += 256) {
        int r = idx >> 6, c = idx & 63;
        Qs[r * FPAD + c] = Q[(size_t)(ib * 64 + r) * HID + qh * 64 + c];
    }
    if (tid < 64) { m_s[tid] = -1e30f; l_s[tid] = 0.f; }

    float acc[4][4];
#pragma unroll
    for (int i = 0; i < 4; i++)
#pragma unroll
        for (int j = 0; j < 4; j++) acc[i][j] = 0.f;

    for (int jb = 0; jb <= ib; jb++) {
        __syncthreads();
        for (int idx = tid; idx < 4096; idx += 256) {
            int r = idx >> 6, c = idx & 63;
            size_t g = (size_t)(jb * 64 + r) * KVD + kh * 64 + c;
            Ks[r * FPAD + c] = K[g];
            Vs[r * FPAD + c] = V[g];
        }
        __syncthreads();

        float s[4][4];
#pragma unroll
        for (int i = 0; i < 4; i++)
#pragma unroll
            for (int j = 0; j < 4; j++) s[i][j] = 0.f;
#pragma unroll 8
        for (int k = 0; k < 64; k++) {
            float qv[4], kv[4];
#pragma unroll
            for (int i = 0; i < 4; i++) qv[i] = Qs[(row0 + i) * FPAD + k];
#pragma unroll
            for (int j = 0; j < 4; j++) kv[j] = Ks[(col0 + j) * FPAD + k];
#pragma unroll
            for (int i = 0; i < 4; i++)
#pragma unroll
                for (int j = 0; j < 4; j++) s[i][j] = fmaf(qv[i], kv[j], s[i][j]);
        }

        const bool diag = (jb == ib);
#pragma unroll
        for (int i = 0; i < 4; i++)
#pragma unroll
            for (int j = 0; j < 4; j++) {
                s[i][j] *= scale;
                if (diag && (col0 + j) > (row0 + i)) s[i][j] = -1e30f;
            }

#pragma unroll
        for (int i = 0; i < 4; i++) {
            float mx = fmaxf(fmaxf(s[i][0], s[i][1]), fmaxf(s[i][2], s[i][3]));
            red[(row0 + i) * 16 + tx] = mx;
        }
        __syncthreads();
        if (tid < 64) {
            float mx = red[tid * 16];
#pragma unroll
            for (int t = 1; t < 16; t++) mx = fmaxf(mx, red[tid * 16 + t]);
            float mold = m_s[tid];
            float mnew = fmaxf(mold, mx);
            al_s[tid] = __expf(mold - mnew);
            m_s[tid] = mnew;
        }
        __syncthreads();

#pragma unroll
        for (int i = 0; i < 4; i++) {
            float mrow = m_s[row0 + i];
            float al = al_s[row0 + i];
            float rs = 0.f;
#pragma unroll
            for (int j = 0; j < 4; j++) {
                float p = __expf(s[i][j] - mrow);
                Ps[(row0 + i) * FPAD + col0 + j] = p;
                rs += p;
            }
            red[(row0 + i) * 16 + tx] = rs;
#pragma unroll
            for (int j = 0; j < 4; j++) acc[i][j] *= al;
        }
        __syncthreads();
        if (tid < 64) {
            float ssum = 0.f;
#pragma unroll
            for (int t = 0; t < 16; t++) ssum += red[tid * 16 + t];
            l_s[tid] = l_s[tid] * al_s[tid] + ssum;
        }

#pragma unroll 8
        for (int j = 0; j < 64; j++) {
            float pv[4], vv[4];
#pragma unroll
            for (int i = 0; i < 4; i++) pv[i] = Ps[(row0 + i) * FPAD + j];
#pragma unroll
            for (int c = 0; c < 4; c++) vv[c] = Vs[j * FPAD + col0 + c];
#pragma unroll
            for (int i = 0; i < 4; i++)
#pragma unroll
                for (int c = 0; c < 4; c++) acc[i][c] = fmaf(pv[i], vv[c], acc[i][c]);
        }
    }
    __syncthreads();

#pragma unroll
    for (int i = 0; i < 4; i++) {
        float inv_l = 1.0f / l_s[row0 + i];
#pragma unroll
        for (int c = 0; c < 4; c++) {
            O[(size_t)(ib * 64 + row0 + i) * HID + qh * 64 + col0 + c] = acc[i][c] * inv_l;
        }
    }
}

// ---------------------------------------------------------------------------
extern "C" void kernel_launch(void* const* d_in, const int* in_sizes, int n_in,
                              void* d_out, int out_size) {
    const float* x        = (const float*)d_in[0];
    const float* q_proj   = (const float*)d_in[1];
    const float* k_proj   = (const float*)d_in[2];
    const float* v_proj   = (const float*)d_in[3];
    const float* o_proj   = (const float*)d_in[4];
    const float* inv_freq = (const float*)d_in[5];
    float* out = (float*)d_out;

    float *Qb, *Kb, *Vb, *Ob;
    __nv_bfloat16 *Ahi, *Alo, *Whi, *Wlo;
    cudaGetSymbolAddress((void**)&Qb, g_Q);
    cudaGetSymbolAddress((void**)&Kb, g_K);
    cudaGetSymbolAddress((void**)&Vb, g_V);
    cudaGetSymbolAddress((void**)&Ob, g_O);
    cudaGetSymbolAddress((void**)&Ahi, g_Ahi);
    cudaGetSymbolAddress((void**)&Alo, g_Alo);
    cudaGetSymbolAddress((void**)&Whi, g_Whi);
    cudaGetSymbolAddress((void**)&Wlo, g_Wlo);

    cudaFuncSetAttribute(gemm_mma, cudaFuncAttributeMaxDynamicSharedMemorySize, G_SMEM);

    const int convBlocks = (SEQ * HID / 4) / 256;

    // x -> bf16 hi/lo
    convert_hl<<<convBlocks, 256>>>(x, Ahi, Alo);

    // Q = x @ q_proj
    transpose_hl<<<dim3(HID / 32, HID / 32), 256>>>(q_proj, Whi, Wlo, HID, HID);
    gemm_mma<<<dim3(HID / 128, SEQ / 128), 256, G_SMEM>>>(Ahi, Alo, Whi, Wlo, Qb, SEQ, HID, HID);

    // K = x @ k_proj
    transpose_hl<<<dim3(KVD / 32, HID / 32), 256>>>(k_proj, Whi, Wlo, HID, KVD);
    gemm_mma<<<dim3(KVD / 128, SEQ / 128), 256, G_SMEM>>>(Ahi, Alo, Whi, Wlo, Kb, SEQ, KVD, HID);

    // V = x @ v_proj
    transpose_hl<<<dim3(KVD / 32, HID / 32), 256>>>(v_proj, Whi, Wlo, HID, KVD);
    gemm_mma<<<dim3(KVD / 128, SEQ / 128), 256, G_SMEM>>>(Ahi, Alo, Whi, Wlo, Vb, SEQ, KVD, HID);

    // RoPE
    rope_kernel<<<SEQ * NQH / 8, 256>>>(Qb, inv_freq, NQH);
    rope_kernel<<<SEQ * NKH / 8, 256>>>(Kb, inv_freq, NKH);

    // Flash attention
    const int fsmem = (4 * 64 * FPAD + 64 * 16 + 3 * 64) * sizeof(float);
    cudaFuncSetAttribute(flash_attn, cudaFuncAttributeMaxDynamicSharedMemorySize, fsmem);
    flash_attn<<<dim3(SEQ / 64, NQH), 256, fsmem>>>(Qb, Kb, Vb, Ob);

    // out = O @ o_proj
    convert_hl<<<convBlocks, 256>>>(Ob, Ahi, Alo);
    transpose_hl<<<dim3(HID / 32, HID / 32), 256>>>(o_proj, Whi, Wlo, HID, HID);
    gemm_mma<<<dim3(HID / 128, SEQ / 128), 256, G_SMEM>>>(Ahi, Alo, Whi, Wlo, out, SEQ, HID, HID);
}

// round 4
// speedup vs baseline: 2.7828x; 1.6061x over previous
#include <cuda_runtime.h>
#include <cuda_bf16.h>
#include <math.h>
#include <cstdint>

#define SEQ 2048
#define HID 2048
#define KVD 512
#define NQH 32
#define NKH 8

// ---------------- scratch (no allocations allowed) ----------------
__device__ float g_Q[SEQ * HID];
__device__ float g_K[SEQ * KVD];
__device__ float g_V[SEQ * KVD];
__device__ float g_O[SEQ * HID];
__device__ __nv_bfloat16 g_Ahi[SEQ * HID];
__device__ __nv_bfloat16 g_Alo[SEQ * HID];
__device__ __nv_bfloat16 g_Whi[HID * HID];   // transposed weights [N,K]
__device__ __nv_bfloat16 g_Wlo[HID * HID];
__device__ __nv_bfloat16 g_Khi[SEQ * KVD];
__device__ __nv_bfloat16 g_Klo[SEQ * KVD];
__device__ __nv_bfloat16 g_Vhi[SEQ * KVD];
__device__ __nv_bfloat16 g_Vlo[SEQ * KVD];

// ---------------- helpers ----------------
__device__ __forceinline__ uint32_t smem_u32(const void* p) {
    uint32_t a;
    asm("{ .reg .u64 t; cvta.to.shared.u64 t, %1; cvt.u32.u64 %0, t; }" : "=r"(a) : "l"(p));
    return a;
}

#define LDSM4(r0, r1, r2, r3, addr) \
    asm volatile("ldmatrix.sync.aligned.m8n8.x4.shared.b16 {%0,%1,%2,%3}, [%4];" \
        : "=r"(r0), "=r"(r1), "=r"(r2), "=r"(r3) : "r"(addr))

#define LDSM4T(r0, r1, r2, r3, addr) \
    asm volatile("ldmatrix.sync.aligned.m8n8.x4.trans.shared.b16 {%0,%1,%2,%3}, [%4];" \
        : "=r"(r0), "=r"(r1), "=r"(r2), "=r"(r3) : "r"(addr))

#define MMA16816(d, a, b0, b1) \
    asm volatile("mma.sync.aligned.m16n8k16.row.col.f32.bf16.bf16.f32 " \
        "{%0,%1,%2,%3},{%4,%5,%6,%7},{%8,%9},{%0,%1,%2,%3};" \
        : "+f"((d)[0]), "+f"((d)[1]), "+f"((d)[2]), "+f"((d)[3]) \
        : "r"((a)[0]), "r"((a)[1]), "r"((a)[2]), "r"((a)[3]), "r"(b0), "r"(b1))

#define CP_ASYNC16(dst, src) \
    asm volatile("cp.async.cg.shared.global [%0], [%1], 16;" :: "r"(dst), "l"(src))
#define CP_COMMIT() asm volatile("cp.async.commit_group;" ::: "memory")
#define CP_WAIT0()  asm volatile("cp.async.wait_group 0;" ::: "memory")

// ---------------- split-convert kernels ----------------
__device__ __forceinline__ uint32_t pack_bf2(__nv_bfloat16 a, __nv_bfloat16 b) {
    __nv_bfloat162 t(a, b);
    return *reinterpret_cast<uint32_t*>(&t);
}

__global__ __launch_bounds__(256) void convert_hl(const float* __restrict__ X,
                                                  __nv_bfloat16* __restrict__ hi,
                                                  __nv_bfloat16* __restrict__ lo) {
    int i = blockIdx.x * 256 + threadIdx.x;
    float4 v = *(const float4*)(X + (size_t)i * 4);
    __nv_bfloat16 h0 = __float2bfloat16_rn(v.x), h1 = __float2bfloat16_rn(v.y);
    __nv_bfloat16 h2 = __float2bfloat16_rn(v.z), h3 = __float2bfloat16_rn(v.w);
    __nv_bfloat16 l0 = __float2bfloat16_rn(v.x - __bfloat162float(h0));
    __nv_bfloat16 l1 = __float2bfloat16_rn(v.y - __bfloat162float(h1));
    __nv_bfloat16 l2 = __float2bfloat16_rn(v.z - __bfloat162float(h2));
    __nv_bfloat16 l3 = __float2bfloat16_rn(v.w - __bfloat162float(h3));
    *(uint2*)(hi + (size_t)i * 4) = make_uint2(pack_bf2(h0, h1), pack_bf2(h2, h3));
    *(uint2*)(lo + (size_t)i * 4) = make_uint2(pack_bf2(l0, l1), pack_bf2(l2, l3));
}

// W [K,N] fp32 -> Wt hi/lo [N,K] bf16
__global__ __launch_bounds__(256) void transpose_hl(const float* __restrict__ W,
                                                    __nv_bfloat16* __restrict__ thi,
                                                    __nv_bfloat16* __restrict__ tlo,
                                                    int K, int N) {
    __shared__ float t[32][33];
    int tx = threadIdx.x & 31, ty = threadIdx.x >> 5;
    int k0 = blockIdx.y * 32, n0 = blockIdx.x * 32;
#pragma unroll
    for (int i = 0; i < 4; i++)
        t[ty + i * 8][tx] = W[(size_t)(k0 + ty + i * 8) * N + n0 + tx];
    __syncthreads();
#pragma unroll
    for (int i = 0; i < 4; i++) {
        float v = t[tx][ty + i * 8];
        __nv_bfloat16 h = __float2bfloat16_rn(v);
        __nv_bfloat16 l = __float2bfloat16_rn(v - __bfloat162float(h));
        size_t o = (size_t)(n0 + ty + i * 8) * K + k0 + tx;
        thi[o] = h;
        tlo[o] = l;
    }
}

// RoPE + scale + hi/lo split (warp per (s,h))
__global__ __launch_bounds__(256) void rope_conv(const float* __restrict__ X,
                                                 __nv_bfloat16* __restrict__ hi,
                                                 __nv_bfloat16* __restrict__ lo,
                                                 const float* __restrict__ inv_freq,
                                                 int heads, float scale) {
    int idx = blockIdx.x * 8 + (threadIdx.x >> 5);
    int j = threadIdx.x & 31;
    int s = idx / heads;
    int h = idx - s * heads;
    const float* p = X + (size_t)s * heads * 64 + h * 64;
    float angle = (float)s * inv_freq[j];
    float sn = sinf(angle), cs = cosf(angle);
    float a = p[j], b = p[32 + j];
    float r0 = (a * cs + b * sn) * scale;
    float r1 = (a * sn - b * cs) * scale;
    size_t o = (size_t)s * heads * 64 + h * 64;
    __nv_bfloat16 h0 = __float2bfloat16_rn(r0);
    __nv_bfloat16 h1 = __float2bfloat16_rn(r1);
    hi[o + j] = h0;
    hi[o + 32 + j] = h1;
    lo[o + j] = __float2bfloat16_rn(r0 - __bfloat162float(h0));
    lo[o + 32 + j] = __float2bfloat16_rn(r1 - __bfloat162float(h1));
}

// ---------------- mma.sync GEMM (unchanged from R3, passing) ----------------
#define TILE_B 10240
#define BUF_B  40960
#define G_SMEM (2 * BUF_B)

__device__ __forceinline__ void tile_async(uint32_t dst, const __nv_bfloat16* src,
                                           int ldk, int tid) {
#pragma unroll
    for (int t = 0; t < 2; t++) {
        int i = tid + t * 256;
        int r = i >> 2, q = i & 3;
        const void* g = src + (size_t)r * ldk + q * 8;
        CP_ASYNC16(dst + r * 80 + q * 16, g);
    }
}

__global__ __launch_bounds__(256, 1) void gemm_mma(
    const __nv_bfloat16* __restrict__ Ahi, const __nv_bfloat16* __restrict__ Alo,
    const __nv_bfloat16* __restrict__ Bhi, const __nv_bfloat16* __restrict__ Blo,
    float* __restrict__ C, int M, int N, int K) {
    extern __shared__ char smem[];
    const uint32_t sb = smem_u32(smem);
    const int tid = threadIdx.x;
    const int w = tid >> 5;
    const int lane = tid & 31;
    const int wm = (w & 1) * 64;
    const int wn = (w >> 1) * 32;
    const int m0 = blockIdx.y * 128;
    const int n0 = blockIdx.x * 128;

    const int a_row = lane & 15;
    const int a_kh = (lane >> 4) & 1;
    const int b_n = (lane & 7) + ((lane >> 4) << 3);
    const int b_kh = (lane >> 3) & 1;

    float acc[4][4][4];
#pragma unroll
    for (int i = 0; i < 4; i++)
#pragma unroll
        for (int j = 0; j < 4; j++)
#pragma unroll
            for (int r = 0; r < 4; r++) acc[i][j][r] = 0.f;

    const int NC = K >> 5;
    {
        const size_t ak = (size_t)m0 * K;
        const size_t bk = (size_t)n0 * K;
        tile_async(sb,              Ahi + ak, K, tid);
        tile_async(sb + TILE_B,     Alo + ak, K, tid);
        tile_async(sb + 2 * TILE_B, Bhi + bk, K, tid);
        tile_async(sb + 3 * TILE_B, Blo + bk, K, tid);
        CP_COMMIT();
    }

    for (int c = 0; c < NC; c++) {
        CP_WAIT0();
        __syncthreads();
        if (c + 1 < NC) {
            const uint32_t nb = sb + ((c + 1) & 1) * BUF_B;
            const size_t ak = (size_t)m0 * K + (size_t)(c + 1) * 32;
            const size_t bk = (size_t)n0 * K + (size_t)(c + 1) * 32;
            tile_async(nb,              Ahi + ak, K, tid);
            tile_async(nb + TILE_B,     Alo + ak, K, tid);
            tile_async(nb + 2 * TILE_B, Bhi + bk, K, tid);
            tile_async(nb + 3 * TILE_B, Blo + bk, K, tid);
            CP_COMMIT();
        }
        const uint32_t base = sb + (c & 1) * BUF_B;

#pragma unroll
        for (int ks = 0; ks < 32; ks += 16) {
            uint32_t ah[4][4], al[4][4], bh[2][4], bl[2][4];
            const uint32_t aoff = (uint32_t)((wm + a_row) * 80 + (ks + a_kh * 8) * 2);
            const uint32_t boff = (uint32_t)((wn + b_n) * 80 + (ks + b_kh * 8) * 2);
#pragma unroll
            for (int mt = 0; mt < 4; mt++) {
                LDSM4(ah[mt][0], ah[mt][1], ah[mt][2], ah[mt][3],
                      base + aoff + mt * 16 * 80);
                LDSM4(al[mt][0], al[mt][1], al[mt][2], al[mt][3],
                      base + TILE_B + aoff + mt * 16 * 80);
            }
#pragma unroll
            for (int np = 0; np < 2; np++) {
                LDSM4(bh[np][0], bh[np][1], bh[np][2], bh[np][3],
                      base + 2 * TILE_B + boff + np * 16 * 80);
                LDSM4(bl[np][0], bl[np][1], bl[np][2], bl[np][3],
                      base + 3 * TILE_B + boff + np * 16 * 80);
            }
#pragma unroll
            for (int mt = 0; mt < 4; mt++)
#pragma unroll
                for (int np = 0; np < 2; np++) {
                    MMA16816(acc[mt][np * 2 + 0], ah[mt], bh[np][0], bh[np][1]);
                    MMA16816(acc[mt][np * 2 + 1], ah[mt], bh[np][2], bh[np][3]);
                    MMA16816(acc[mt][np * 2 + 0], ah[mt], bl[np][0], bl[np][1]);
                    MMA16816(acc[mt][np * 2 + 1], ah[mt], bl[np][2], bl[np][3]);
                    MMA16816(acc[mt][np * 2 + 0], al[mt], bh[np][0], bh[np][1]);
                    MMA16816(acc[mt][np * 2 + 1], al[mt], bh[np][2], bh[np][3]);
                }
        }
    }

    const int g = lane >> 2, c2 = lane & 3;
#pragma unroll
    for (int mt = 0; mt < 4; mt++) {
        const int row = m0 + wm + mt * 16 + g;
#pragma unroll
        for (int nt = 0; nt < 4; nt++) {
            const int col = n0 + wn + nt * 8 + c2 * 2;
            *(float2*)&C[(size_t)row * N + col] =
                make_float2(acc[mt][nt][0], acc[mt][nt][1]);
            *(float2*)&C[(size_t)(row + 8) * N + col] =
                make_float2(acc[mt][nt][2], acc[mt][nt][3]);
        }
    }
}

// ---------------- tensor-core flash attention ----------------
// smem: Qhi(0) Qlo(18432) | Khi(36864) Klo(46080) Vhi(55296) Vlo(64512)
#define FQ_H 0
#define FQ_L 18432
#define FK_H 36864
#define F_SMEM 73728

__device__ __forceinline__ void pack_hl(float p0, float p1, uint32_t& hi, uint32_t& lo) {
    __nv_bfloat162 h = __floats2bfloat162_rn(p0, p1);
    hi = *reinterpret_cast<uint32_t*>(&h);
    __nv_bfloat162 l = __floats2bfloat162_rn(p0 - __bfloat162float(h.x),
                                             p1 - __bfloat162float(h.y));
    lo = *reinterpret_cast<uint32_t*>(&l);
}

__global__ __launch_bounds__(256, 2) void flash_mma(
    const __nv_bfloat16* __restrict__ Qhi, const __nv_bfloat16* __restrict__ Qlo,
    const __nv_bfloat16* __restrict__ Khi, const __nv_bfloat16* __restrict__ Klo,
    const __nv_bfloat16* __restrict__ Vhi, const __nv_bfloat16* __restrict__ Vlo,
    float* __restrict__ O) {
    extern __shared__ char smem[];
    const uint32_t sb = smem_u32(smem);
    const int tid = threadIdx.x;
    const int lane = tid & 31;
    const int w = tid >> 5;
    const int ib = gridDim.x - 1 - blockIdx.x;  // long blocks first
    const int qh = blockIdx.y;
    const int kh = qh >> 2;
    const int qbase = ib * 128;

    // Q tile -> smem (hi/lo), 144B padded rows
#pragma unroll
    for (int i = 0; i < 8; i++) {
        int idx = tid + i * 256;
        int sub = idx >> 10, r = (idx >> 3) & 127, q = idx & 7;
        const __nv_bfloat16* src = (sub ? Qlo : Qhi) + (size_t)(qbase + r) * HID + qh * 64 + q * 8;
        CP_ASYNC16(sb + sub * 18432 + r * 144 + q * 16, src);
    }
    CP_COMMIT();

    const int a_row = lane & 15, a_kh = lane >> 4;
    const int b_n = (lane & 7) + ((lane >> 4) << 3), b_kh = (lane >> 3) & 1;
    const int v_k = (lane & 7) + ((lane >> 3) & 1) * 8, v_n = (lane >> 4) * 8;
    const int g = lane >> 2, tg = lane & 3;

    float o[8][4];
#pragma unroll
    for (int nt = 0; nt < 8; nt++)
#pragma unroll
        for (int r = 0; r < 4; r++) o[nt][r] = 0.f;
    float m0 = -1e30f, m1 = -1e30f, l0 = 0.f, l1 = 0.f;

    const int jbmax = 2 * ib + 1;
    for (int jb = 0; jb <= jbmax; jb++) {
        __syncthreads();
        // K/V tiles (hi/lo): 4 sub-tiles of 64x64 bf16
#pragma unroll
        for (int i = 0; i < 8; i++) {
            int idx = tid + i * 256;
            int sub = idx >> 9, r = (idx >> 3) & 63, q = idx & 7;
            const __nv_bfloat16* base = (sub == 0) ? Khi : (sub == 1) ? Klo
                                       : (sub == 2) ? Vhi : Vlo;
            const __nv_bfloat16* src = base + (size_t)(jb * 64 + r) * KVD + kh * 64 + q * 8;
            CP_ASYNC16(sb + FK_H + sub * 9216 + r * 144 + q * 16, src);
        }
        CP_COMMIT();
        CP_WAIT0();
        __syncthreads();

        // S = Q K^T (3-pass split)
        float s[8][4];
#pragma unroll
        for (int nt = 0; nt < 8; nt++)
#pragma unroll
            for (int r = 0; r < 4; r++) s[nt][r] = 0.f;
#pragma unroll
        for (int kc = 0; kc < 4; kc++) {
            uint32_t ah[4], al[4];
            const uint32_t aoff = (w * 16 + a_row) * 144 + (kc * 16 + a_kh * 8) * 2;
            LDSM4(ah[0], ah[1], ah[2], ah[3], sb + FQ_H + aoff);
            LDSM4(al[0], al[1], al[2], al[3], sb + FQ_L + aoff);
#pragma unroll
            for (int n2 = 0; n2 < 4; n2++) {
                uint32_t bh[4], bl[4];
                const uint32_t boff = (n2 * 16 + b_n) * 144 + (kc * 16 + b_kh * 8) * 2;
                LDSM4(bh[0], bh[1], bh[2], bh[3], sb + FK_H + boff);
                LDSM4(bl[0], bl[1], bl[2], bl[3], sb + FK_H + 9216 + boff);
                MMA16816(s[n2 * 2 + 0], ah, bh[0], bh[1]);
                MMA16816(s[n2 * 2 + 1], ah, bh[2], bh[3]);
                MMA16816(s[n2 * 2 + 0], ah, bl[0], bl[1]);
                MMA16816(s[n2 * 2 + 1], ah, bl[2], bl[3]);
                MMA16816(s[n2 * 2 + 0], al, bh[0], bh[1]);
                MMA16816(s[n2 * 2 + 1], al, bh[2], bh[3]);
            }
        }

        // causal mask (only the last two chunks can clip)
        if (jb >= 2 * ib) {
            const int row0 = qbase + w * 16 + g;
            const int row1 = row0 + 8;
#pragma unroll
            for (int nt = 0; nt < 8; nt++) {
                const int col = jb * 64 + nt * 8 + tg * 2;
                if (col > row0) s[nt][0] = -1e30f;
                if (col + 1 > row0) s[nt][1] = -1e30f;
                if (col > row1) s[nt][2] = -1e30f;
                if (col + 1 > row1) s[nt][3] = -1e30f;
            }
        }

        // row max
        float mx0 = -1e30f, mx1 = -1e30f;
#pragma unroll
        for (int nt = 0; nt < 8; nt++) {
            mx0 = fmaxf(mx0, fmaxf(s[nt][0], s[nt][1]));
            mx1 = fmaxf(mx1, fmaxf(s[nt][2], s[nt][3]));
        }
        mx0 = fmaxf(mx0, __shfl_xor_sync(0xffffffff, mx0, 1));
        mx0 = fmaxf(mx0, __shfl_xor_sync(0xffffffff, mx0, 2));
        mx1 = fmaxf(mx1, __shfl_xor_sync(0xffffffff, mx1, 1));
        mx1 = fmaxf(mx1, __shfl_xor_sync(0xffffffff, mx1, 2));
        const float mn0 = fmaxf(m0, mx0), mn1 = fmaxf(m1, mx1);
        const float al0 = __expf(m0 - mn0), al1 = __expf(m1 - mn1);
        m0 = mn0; m1 = mn1;

        // P = exp(S - m), row sums, rescale O
        float rs0 = 0.f, rs1 = 0.f;
#pragma unroll
        for (int nt = 0; nt < 8; nt++) {
            s[nt][0] = __expf(s[nt][0] - mn0);
            s[nt][1] = __expf(s[nt][1] - mn0);
            s[nt][2] = __expf(s[nt][2] - mn1);
            s[nt][3] = __expf(s[nt][3] - mn1);
            rs0 += s[nt][0] + s[nt][1];
            rs1 += s[nt][2] + s[nt][3];
            o[nt][0] *= al0; o[nt][1] *= al0;
            o[nt][2] *= al1; o[nt][3] *= al1;
        }
        rs0 += __shfl_xor_sync(0xffffffff, rs0, 1);
        rs0 += __shfl_xor_sync(0xffffffff, rs0, 2);
        rs1 += __shfl_xor_sync(0xffffffff, rs1, 1);
        rs1 += __shfl_xor_sync(0xffffffff, rs1, 2);
        l0 = l0 * al0 + rs0;
        l1 = l1 * al1 + rs1;

        // O += P @ V (3-pass split; P packed from S fragments)
#pragma unroll
        for (int kc2 = 0; kc2 < 4; kc2++) {
            uint32_t aph[4], apl[4];
            pack_hl(s[2 * kc2][0], s[2 * kc2][1], aph[0], apl[0]);
            pack_hl(s[2 * kc2][2], s[2 * kc2][3], aph[1], apl[1]);
            pack_hl(s[2 * kc2 + 1][0], s[2 * kc2 + 1][1], aph[2], apl[2]);
            pack_hl(s[2 * kc2 + 1][2], s[2 * kc2 + 1][3], aph[3], apl[3]);
#pragma unroll
            for (int n2 = 0; n2 < 4; n2++) {
                uint32_t vh[4], vl[4];
                const uint32_t voff = (kc2 * 16 + v_k) * 144 + (n2 * 16 + v_n) * 2;
                LDSM4T(vh[0], vh[1], vh[2], vh[3], sb + FK_H + 2 * 9216 + voff);
                LDSM4T(vl[0], vl[1], vl[2], vl[3], sb + FK_H + 3 * 9216 + voff);
                MMA16816(o[n2 * 2 + 0], aph, vh[0], vh[1]);
                MMA16816(o[n2 * 2 + 1], aph, vh[2], vh[3]);
                MMA16816(o[n2 * 2 + 0], aph, vl[0], vl[1]);
                MMA16816(o[n2 * 2 + 1], aph, vl[2], vl[3]);
                MMA16816(o[n2 * 2 + 0], apl, vh[0], vh[1]);
                MMA16816(o[n2 * 2 + 1], apl, vh[2], vh[3]);
            }
        }
    }

    // epilogue
    const float il0 = 1.0f / l0, il1 = 1.0f / l1;
    const int row0 = qbase + w * 16 + g;
#pragma unroll
    for (int nt = 0; nt < 8; nt++) {
        const int col = qh * 64 + nt * 8 + tg * 2;
        *(float2*)&O[(size_t)row0 * HID + col] = make_float2(o[nt][0] * il0, o[nt][1] * il0);
        *(float2*)&O[(size_t)(row0 + 8) * HID + col] = make_float2(o[nt][2] * il1, o[nt][3] * il1);
    }
}

// ---------------------------------------------------------------------------
extern "C" void kernel_launch(void* const* d_in, const int* in_sizes, int n_in,
                              void* d_out, int out_size) {
    const float* x        = (const float*)d_in[0];
    const float* q_proj   = (const float*)d_in[1];
    const float* k_proj   = (const float*)d_in[2];
    const float* v_proj   = (const float*)d_in[3];
    const float* o_proj   = (const float*)d_in[4];
    const float* inv_freq = (const float*)d_in[5];
    float* out = (float*)d_out;

    float *Qb, *Kb, *Vb, *Ob;
    __nv_bfloat16 *Ahi, *Alo, *Whi, *Wlo, *Khi, *Klo, *Vhi, *Vlo;
    cudaGetSymbolAddress((void**)&Qb, g_Q);
    cudaGetSymbolAddress((void**)&Kb, g_K);
    cudaGetSymbolAddress((void**)&Vb, g_V);
    cudaGetSymbolAddress((void**)&Ob, g_O);
    cudaGetSymbolAddress((void**)&Ahi, g_Ahi);
    cudaGetSymbolAddress((void**)&Alo, g_Alo);
    cudaGetSymbolAddress((void**)&Whi, g_Whi);
    cudaGetSymbolAddress((void**)&Wlo, g_Wlo);
    cudaGetSymbolAddress((void**)&Khi, g_Khi);
    cudaGetSymbolAddress((void**)&Klo, g_Klo);
    cudaGetSymbolAddress((void**)&Vhi, g_Vhi);
    cudaGetSymbolAddress((void**)&Vlo, g_Vlo);

    cudaFuncSetAttribute(gemm_mma, cudaFuncAttributeMaxDynamicSharedMemorySize, G_SMEM);
    cudaFuncSetAttribute(flash_mma, cudaFuncAttributeMaxDynamicSharedMemorySize, F_SMEM);

    const int convBlocks = (SEQ * HID / 4) / 256;

    // x -> bf16 hi/lo
    convert_hl<<<convBlocks, 256>>>(x, Ahi, Alo);

    // projections
    transpose_hl<<<dim3(HID / 32, HID / 32), 256>>>(q_proj, Whi, Wlo, HID, HID);
    gemm_mma<<<dim3(HID / 128, SEQ / 128), 256, G_SMEM>>>(Ahi, Alo, Whi, Wlo, Qb, SEQ, HID, HID);
    transpose_hl<<<dim3(KVD / 32, HID / 32), 256>>>(k_proj, Whi, Wlo, HID, KVD);
    gemm_mma<<<dim3(KVD / 128, SEQ / 128), 256, G_SMEM>>>(Ahi, Alo, Whi, Wlo, Kb, SEQ, KVD, HID);
    transpose_hl<<<dim3(KVD / 32, HID / 32), 256>>>(v_proj, Whi, Wlo, HID, KVD);
    gemm_mma<<<dim3(KVD / 128, SEQ / 128), 256, G_SMEM>>>(Ahi, Alo, Whi, Wlo, Vb, SEQ, KVD, HID);

    // RoPE + split (Q pre-scaled by 1/sqrt(64)); V split
    rope_conv<<<SEQ * NQH / 8, 256>>>(Qb, Ahi, Alo, inv_freq, NQH, 0.125f);  // Ahi/Alo reused as Q hi/lo
    rope_conv<<<SEQ * NKH / 8, 256>>>(Kb, Khi, Klo, inv_freq, NKH, 1.0f);
    convert_hl<<<(SEQ * KVD / 4) / 256, 256>>>(Vb, Vhi, Vlo);

    // tensor-core flash attention
    flash_mma<<<dim3(SEQ / 128, NQH), 256, F_SMEM>>>(Ahi, Alo, Khi, Klo, Vhi, Vlo, Ob);

    // out = O @ o_proj
    convert_hl<<<convBlocks, 256>>>(Ob, Ahi, Alo);
    transpose_hl<<<dim3(HID / 32, HID / 32), 256>>>(o_proj, Whi, Wlo, HID, HID);
    gemm_mma<<<dim3(HID / 128, SEQ / 128), 256, G_SMEM>>>(Ahi, Alo, Whi, Wlo, out, SEQ, HID, HID);
}

// round 5
// speedup vs baseline: 3.1496x; 1.1318x over previous
#include <cuda_runtime.h>
#include <cuda_bf16.h>
#include <math.h>
#include <cstdint>

#define SEQ 2048
#define HID 2048
#define KVD 512
#define QKVN 3072
#define NQH 32
#define NKH 8

// ---------------- scratch (no allocations allowed) ----------------
__device__ float g_QKV[SEQ * QKVN];
__device__ float g_O[SEQ * HID];
__device__ __nv_bfloat16 g_Ahi[SEQ * HID];
__device__ __nv_bfloat16 g_Alo[SEQ * HID];
__device__ __nv_bfloat16 g_Whi[QKVN * HID];   // transposed weights [N,K]
__device__ __nv_bfloat16 g_Wlo[QKVN * HID];
__device__ __nv_bfloat16 g_Khi[SEQ * KVD];
__device__ __nv_bfloat16 g_Klo[SEQ * KVD];
__device__ __nv_bfloat16 g_Vhi[SEQ * KVD];
__device__ __nv_bfloat16 g_Vlo[SEQ * KVD];

// ---------------- helpers ----------------
__device__ __forceinline__ uint32_t smem_u32(const void* p) {
    uint32_t a;
    asm("{ .reg .u64 t; cvta.to.shared.u64 t, %1; cvt.u32.u64 %0, t; }" : "=r"(a) : "l"(p));
    return a;
}

#define LDSM4(r0, r1, r2, r3, addr) \
    asm volatile("ldmatrix.sync.aligned.m8n8.x4.shared.b16 {%0,%1,%2,%3}, [%4];" \
        : "=r"(r0), "=r"(r1), "=r"(r2), "=r"(r3) : "r"(addr))

#define LDSM4T(r0, r1, r2, r3, addr) \
    asm volatile("ldmatrix.sync.aligned.m8n8.x4.trans.shared.b16 {%0,%1,%2,%3}, [%4];" \
        : "=r"(r0), "=r"(r1), "=r"(r2), "=r"(r3) : "r"(addr))

#define MMA16816(d, a, b0, b1) \
    asm volatile("mma.sync.aligned.m16n8k16.row.col.f32.bf16.bf16.f32 " \
        "{%0,%1,%2,%3},{%4,%5,%6,%7},{%8,%9},{%0,%1,%2,%3};" \
        : "+f"((d)[0]), "+f"((d)[1]), "+f"((d)[2]), "+f"((d)[3]) \
        : "r"((a)[0]), "r"((a)[1]), "r"((a)[2]), "r"((a)[3]), "r"(b0), "r"(b1))

#define CP_ASYNC16(dst, src) \
    asm volatile("cp.async.cg.shared.global [%0], [%1], 16;" :: "r"(dst), "l"(src))
#define CP_COMMIT() asm volatile("cp.async.commit_group;" ::: "memory")
#define CP_WAIT0()  asm volatile("cp.async.wait_group 0;" ::: "memory")

// ---------------- split-convert kernels ----------------
__device__ __forceinline__ uint32_t pack_bf2(__nv_bfloat16 a, __nv_bfloat16 b) {
    __nv_bfloat162 t(a, b);
    return *reinterpret_cast<uint32_t*>(&t);
}

__global__ __launch_bounds__(256) void convert_hl(const float* __restrict__ X,
                                                  __nv_bfloat16* __restrict__ hi,
                                                  __nv_bfloat16* __restrict__ lo) {
    int i = blockIdx.x * 256 + threadIdx.x;
    float4 v = *(const float4*)(X + (size_t)i * 4);
    __nv_bfloat16 h0 = __float2bfloat16_rn(v.x), h1 = __float2bfloat16_rn(v.y);
    __nv_bfloat16 h2 = __float2bfloat16_rn(v.z), h3 = __float2bfloat16_rn(v.w);
    __nv_bfloat16 l0 = __float2bfloat16_rn(v.x - __bfloat162float(h0));
    __nv_bfloat16 l1 = __float2bfloat16_rn(v.y - __bfloat162float(h1));
    __nv_bfloat16 l2 = __float2bfloat16_rn(v.z - __bfloat162float(h2));
    __nv_bfloat16 l3 = __float2bfloat16_rn(v.w - __bfloat162float(h3));
    *(uint2*)(hi + (size_t)i * 4) = make_uint2(pack_bf2(h0, h1), pack_bf2(h2, h3));
    *(uint2*)(lo + (size_t)i * 4) = make_uint2(pack_bf2(l0, l1), pack_bf2(l2, l3));
}

// strided variant: read [SEQ, ld] slab starting at column col0, write packed [SEQ, cols]
__global__ __launch_bounds__(256) void convert_hl_strided(const float* __restrict__ X,
                                                          __nv_bfloat16* __restrict__ hi,
                                                          __nv_bfloat16* __restrict__ lo,
                                                          int ld, int col0, int cols) {
    int i = blockIdx.x * 256 + threadIdx.x;
    int r = i / (cols / 4), q = i % (cols / 4);
    float4 v = *(const float4*)(X + (size_t)r * ld + col0 + q * 4);
    __nv_bfloat16 h0 = __float2bfloat16_rn(v.x), h1 = __float2bfloat16_rn(v.y);
    __nv_bfloat16 h2 = __float2bfloat16_rn(v.z), h3 = __float2bfloat16_rn(v.w);
    __nv_bfloat16 l0 = __float2bfloat16_rn(v.x - __bfloat162float(h0));
    __nv_bfloat16 l1 = __float2bfloat16_rn(v.y - __bfloat162float(h1));
    __nv_bfloat16 l2 = __float2bfloat16_rn(v.z - __bfloat162float(h2));
    __nv_bfloat16 l3 = __float2bfloat16_rn(v.w - __bfloat162float(h3));
    size_t o = (size_t)r * cols + q * 4;
    *(uint2*)(hi + o) = make_uint2(pack_bf2(h0, h1), pack_bf2(h2, h3));
    *(uint2*)(lo + o) = make_uint2(pack_bf2(l0, l1), pack_bf2(l2, l3));
}

// W [K,N] fp32 -> Wt hi/lo [N,K] bf16
__global__ __launch_bounds__(256) void transpose_hl(const float* __restrict__ W,
                                                    __nv_bfloat16* __restrict__ thi,
                                                    __nv_bfloat16* __restrict__ tlo,
                                                    int K, int N) {
    __shared__ float t[32][33];
    int tx = threadIdx.x & 31, ty = threadIdx.x >> 5;
    int k0 = blockIdx.y * 32, n0 = blockIdx.x * 32;
#pragma unroll
    for (int i = 0; i < 4; i++)
        t[ty + i * 8][tx] = W[(size_t)(k0 + ty + i * 8) * N + n0 + tx];
    __syncthreads();
#pragma unroll
    for (int i = 0; i < 4; i++) {
        float v = t[tx][ty + i * 8];
        __nv_bfloat16 h = __float2bfloat16_rn(v);
        __nv_bfloat16 l = __float2bfloat16_rn(v - __bfloat162float(h));
        size_t o = (size_t)(n0 + ty + i * 8) * K + k0 + tx;
        thi[o] = h;
        tlo[o] = l;
    }
}

// RoPE + scale + hi/lo split (warp per (s,h)); reads strided slab, writes packed
__global__ __launch_bounds__(256) void rope_conv(const float* __restrict__ X,
                                                 __nv_bfloat16* __restrict__ hi,
                                                 __nv_bfloat16* __restrict__ lo,
                                                 const float* __restrict__ inv_freq,
                                                 int heads, float scale, int ld, int col0) {
    int idx = blockIdx.x * 8 + (threadIdx.x >> 5);
    int j = threadIdx.x & 31;
    int s = idx / heads;
    int h = idx - s * heads;
    const float* p = X + (size_t)s * ld + col0 + h * 64;
    float angle = (float)s * inv_freq[j];
    float sn = sinf(angle), cs = cosf(angle);
    float a = p[j], b = p[32 + j];
    float r0 = (a * cs + b * sn) * scale;
    float r1 = (a * sn - b * cs) * scale;
    size_t o = (size_t)s * heads * 64 + h * 64;
    __nv_bfloat16 h0 = __float2bfloat16_rn(r0);
    __nv_bfloat16 h1 = __float2bfloat16_rn(r1);
    hi[o + j] = h0;
    hi[o + 32 + j] = h1;
    lo[o + j] = __float2bfloat16_rn(r0 - __bfloat162float(h0));
    lo[o + 32 + j] = __float2bfloat16_rn(r1 - __bfloat162float(h1));
}

// ---------------- mma.sync GEMM, pass-major MMA ordering ----------------
#define TILE_B 10240
#define BUF_B  40960
#define G_SMEM (2 * BUF_B)

__device__ __forceinline__ void tile_async(uint32_t dst, const __nv_bfloat16* src,
                                           int ldk, int tid) {
#pragma unroll
    for (int t = 0; t < 2; t++) {
        int i = tid + t * 256;
        int r = i >> 2, q = i & 3;
        const void* g = src + (size_t)r * ldk + q * 8;
        CP_ASYNC16(dst + r * 80 + q * 16, g);
    }
}

__global__ __launch_bounds__(256, 1) void gemm_mma(
    const __nv_bfloat16* __restrict__ Ahi, const __nv_bfloat16* __restrict__ Alo,
    const __nv_bfloat16* __restrict__ Bhi, const __nv_bfloat16* __restrict__ Blo,
    float* __restrict__ C, int M, int N, int K) {
    extern __shared__ char smem[];
    const uint32_t sb = smem_u32(smem);
    const int tid = threadIdx.x;
    const int w = tid >> 5;
    const int lane = tid & 31;
    const int wm = (w & 1) * 64;
    const int wn = (w >> 1) * 32;
    const int m0 = blockIdx.y * 128;
    const int n0 = blockIdx.x * 128;

    const int a_row = lane & 15;
    const int a_kh = (lane >> 4) & 1;
    const int b_n = (lane & 7) + ((lane >> 4) << 3);
    const int b_kh = (lane >> 3) & 1;

    float acc[4][4][4];
#pragma unroll
    for (int i = 0; i < 4; i++)
#pragma unroll
        for (int j = 0; j < 4; j++)
#pragma unroll
            for (int r = 0; r < 4; r++) acc[i][j][r] = 0.f;

    const int NC = K >> 5;
    {
        const size_t ak = (size_t)m0 * K;
        const size_t bk = (size_t)n0 * K;
        tile_async(sb,              Ahi + ak, K, tid);
        tile_async(sb + TILE_B,     Alo + ak, K, tid);
        tile_async(sb + 2 * TILE_B, Bhi + bk, K, tid);
        tile_async(sb + 3 * TILE_B, Blo + bk, K, tid);
        CP_COMMIT();
    }

    for (int c = 0; c < NC; c++) {
        CP_WAIT0();
        __syncthreads();
        if (c + 1 < NC) {
            const uint32_t nb = sb + ((c + 1) & 1) * BUF_B;
            const size_t ak = (size_t)m0 * K + (size_t)(c + 1) * 32;
            const size_t bk = (size_t)n0 * K + (size_t)(c + 1) * 32;
            tile_async(nb,              Ahi + ak, K, tid);
            tile_async(nb + TILE_B,     Alo + ak, K, tid);
            tile_async(nb + 2 * TILE_B, Bhi + bk, K, tid);
            tile_async(nb + 3 * TILE_B, Blo + bk, K, tid);
            CP_COMMIT();
        }
        const uint32_t base = sb + (c & 1) * BUF_B;

#pragma unroll
        for (int ks = 0; ks < 32; ks += 16) {
            uint32_t ah[4][4], al[4][4], bh[2][4], bl[2][4];
            const uint32_t aoff = (uint32_t)((wm + a_row) * 80 + (ks + a_kh * 8) * 2);
            const uint32_t boff = (uint32_t)((wn + b_n) * 80 + (ks + b_kh * 8) * 2);
#pragma unroll
            for (int mt = 0; mt < 4; mt++) {
                LDSM4(ah[mt][0], ah[mt][1], ah[mt][2], ah[mt][3],
                      base + aoff + mt * 16 * 80);
                LDSM4(al[mt][0], al[mt][1], al[mt][2], al[mt][3],
                      base + TILE_B + aoff + mt * 16 * 80);
            }
#pragma unroll
            for (int np = 0; np < 2; np++) {
                LDSM4(bh[np][0], bh[np][1], bh[np][2], bh[np][3],
                      base + 2 * TILE_B + boff + np * 16 * 80);
                LDSM4(bl[np][0], bl[np][1], bl[np][2], bl[np][3],
                      base + 3 * TILE_B + boff + np * 16 * 80);
            }
            // pass-major: same-accumulator reuse distance = 16 MMAs
#pragma unroll
            for (int mt = 0; mt < 4; mt++)
#pragma unroll
                for (int np = 0; np < 2; np++) {
                    MMA16816(acc[mt][np * 2 + 0], ah[mt], bh[np][0], bh[np][1]);
                    MMA16816(acc[mt][np * 2 + 1], ah[mt], bh[np][2], bh[np][3]);
                }
#pragma unroll
            for (int mt = 0; mt < 4; mt++)
#pragma unroll
                for (int np = 0; np < 2; np++) {
                    MMA16816(acc[mt][np * 2 + 0], ah[mt], bl[np][0], bl[np][1]);
                    MMA16816(acc[mt][np * 2 + 1], ah[mt], bl[np][2], bl[np][3]);
                }
#pragma unroll
            for (int mt = 0; mt < 4; mt++)
#pragma unroll
                for (int np = 0; np < 2; np++) {
                    MMA16816(acc[mt][np * 2 + 0], al[mt], bh[np][0], bh[np][1]);
                    MMA16816(acc[mt][np * 2 + 1], al[mt], bh[np][2], bh[np][3]);
                }
        }
    }

    const int g = lane >> 2, c2 = lane & 3;
#pragma unroll
    for (int mt = 0; mt < 4; mt++) {
        const int row = m0 + wm + mt * 16 + g;
#pragma unroll
        for (int nt = 0; nt < 4; nt++) {
            const int col = n0 + wn + nt * 8 + c2 * 2;
            *(float2*)&C[(size_t)row * N + col] =
                make_float2(acc[mt][nt][0], acc[mt][nt][1]);
            *(float2*)&C[(size_t)(row + 8) * N + col] =
                make_float2(acc[mt][nt][2], acc[mt][nt][3]);
        }
    }
}

// ---------------- tensor-core flash attention ----------------
#define FQ_H 0
#define FQ_L 18432
#define FK_H 36864
#define F_SMEM 73728

__device__ __forceinline__ void pack_hl(float p0, float p1, uint32_t& hi, uint32_t& lo) {
    __nv_bfloat162 h = __floats2bfloat162_rn(p0, p1);
    hi = *reinterpret_cast<uint32_t*>(&h);
    __nv_bfloat162 l = __floats2bfloat162_rn(p0 - __bfloat162float(h.x),
                                             p1 - __bfloat162float(h.y));
    lo = *reinterpret_cast<uint32_t*>(&l);
}

__global__ __launch_bounds__(256, 2) void flash_mma(
    const __nv_bfloat16* __restrict__ Qhi, const __nv_bfloat16* __restrict__ Qlo,
    const __nv_bfloat16* __restrict__ Khi, const __nv_bfloat16* __restrict__ Klo,
    const __nv_bfloat16* __restrict__ Vhi, const __nv_bfloat16* __restrict__ Vlo,
    float* __restrict__ O) {
    extern __shared__ char smem[];
    const uint32_t sb = smem_u32(smem);
    const int tid = threadIdx.x;
    const int lane = tid & 31;
    const int w = tid >> 5;
    const int ib = gridDim.x - 1 - blockIdx.x;
    const int qh = blockIdx.y;
    const int kh = qh >> 2;
    const int qbase = ib * 128;

#pragma unroll
    for (int i = 0; i < 8; i++) {
        int idx = tid + i * 256;
        int sub = idx >> 10, r = (idx >> 3) & 127, q = idx & 7;
        const __nv_bfloat16* src = (sub ? Qlo : Qhi) + (size_t)(qbase + r) * HID + qh * 64 + q * 8;
        CP_ASYNC16(sb + sub * 18432 + r * 144 + q * 16, src);
    }
    CP_COMMIT();

    const int a_row = lane & 15, a_kh = lane >> 4;
    const int b_n = (lane & 7) + ((lane >> 4) << 3), b_kh = (lane >> 3) & 1;
    const int v_k = (lane & 7) + ((lane >> 3) & 1) * 8, v_n = (lane >> 4) * 8;
    const int g = lane >> 2, tg = lane & 3;

    float o[8][4];
#pragma unroll
    for (int nt = 0; nt < 8; nt++)
#pragma unroll
        for (int r = 0; r < 4; r++) o[nt][r] = 0.f;
    float m0 = -1e30f, m1 = -1e30f, l0 = 0.f, l1 = 0.f;

    const int jbmax = 2 * ib + 1;
    for (int jb = 0; jb <= jbmax; jb++) {
        __syncthreads();
#pragma unroll
        for (int i = 0; i < 8; i++) {
            int idx = tid + i * 256;
            int sub = idx >> 9, r = (idx >> 3) & 63, q = idx & 7;
            const __nv_bfloat16* base = (sub == 0) ? Khi : (sub == 1) ? Klo
                                       : (sub == 2) ? Vhi : Vlo;
            const __nv_bfloat16* src = base + (size_t)(jb * 64 + r) * KVD + kh * 64 + q * 8;
            CP_ASYNC16(sb + FK_H + sub * 9216 + r * 144 + q * 16, src);
        }
        CP_COMMIT();
        CP_WAIT0();
        __syncthreads();

        // S = Q K^T (3-pass split, pass-major within n2 pairs)
        float s[8][4];
#pragma unroll
        for (int nt = 0; nt < 8; nt++)
#pragma unroll
            for (int r = 0; r < 4; r++) s[nt][r] = 0.f;
#pragma unroll
        for (int kc = 0; kc < 4; kc++) {
            uint32_t ah[4], al[4];
            const uint32_t aoff = (w * 16 + a_row) * 144 + (kc * 16 + a_kh * 8) * 2;
            LDSM4(ah[0], ah[1], ah[2], ah[3], sb + FQ_H + aoff);
            LDSM4(al[0], al[1], al[2], al[3], sb + FQ_L + aoff);
#pragma unroll
            for (int n2p = 0; n2p < 2; n2p++) {
                uint32_t bh[2][4], bl[2][4];
#pragma unroll
                for (int j = 0; j < 2; j++) {
                    const int n2 = n2p * 2 + j;
                    const uint32_t boff = (n2 * 16 + b_n) * 144 + (kc * 16 + b_kh * 8) * 2;
                    LDSM4(bh[j][0], bh[j][1], bh[j][2], bh[j][3], sb + FK_H + boff);
                    LDSM4(bl[j][0], bl[j][1], bl[j][2], bl[j][3], sb + FK_H + 9216 + boff);
                }
#pragma unroll
                for (int j = 0; j < 2; j++) {
                    const int n2 = n2p * 2 + j;
                    MMA16816(s[n2 * 2 + 0], ah, bh[j][0], bh[j][1]);
                    MMA16816(s[n2 * 2 + 1], ah, bh[j][2], bh[j][3]);
                }
#pragma unroll
                for (int j = 0; j < 2; j++) {
                    const int n2 = n2p * 2 + j;
                    MMA16816(s[n2 * 2 + 0], ah, bl[j][0], bl[j][1]);
                    MMA16816(s[n2 * 2 + 1], ah, bl[j][2], bl[j][3]);
                }
#pragma unroll
                for (int j = 0; j < 2; j++) {
                    const int n2 = n2p * 2 + j;
                    MMA16816(s[n2 * 2 + 0], al, bh[j][0], bh[j][1]);
                    MMA16816(s[n2 * 2 + 1], al, bh[j][2], bh[j][3]);
                }
            }
        }

        if (jb >= 2 * ib) {
            const int row0 = qbase + w * 16 + g;
            const int row1 = row0 + 8;
#pragma unroll
            for (int nt = 0; nt < 8; nt++) {
                const int col = jb * 64 + nt * 8 + tg * 2;
                if (col > row0) s[nt][0] = -1e30f;
                if (col + 1 > row0) s[nt][1] = -1e30f;
                if (col > row1) s[nt][2] = -1e30f;
                if (col + 1 > row1) s[nt][3] = -1e30f;
            }
        }

        float mx0 = -1e30f, mx1 = -1e30f;
#pragma unroll
        for (int nt = 0; nt < 8; nt++) {
            mx0 = fmaxf(mx0, fmaxf(s[nt][0], s[nt][1]));
            mx1 = fmaxf(mx1, fmaxf(s[nt][2], s[nt][3]));
        }
        mx0 = fmaxf(mx0, __shfl_xor_sync(0xffffffff, mx0, 1));
        mx0 = fmaxf(mx0, __shfl_xor_sync(0xffffffff, mx0, 2));
        mx1 = fmaxf(mx1, __shfl_xor_sync(0xffffffff, mx1, 1));
        mx1 = fmaxf(mx1, __shfl_xor_sync(0xffffffff, mx1, 2));
        const float mn0 = fmaxf(m0, mx0), mn1 = fmaxf(m1, mx1);
        const float al0 = __expf(m0 - mn0), al1 = __expf(m1 - mn1);
        m0 = mn0; m1 = mn1;

        float rs0 = 0.f, rs1 = 0.f;
#pragma unroll
        for (int nt = 0; nt < 8; nt++) {
            s[nt][0] = __expf(s[nt][0] - mn0);
            s[nt][1] = __expf(s[nt][1] - mn0);
            s[nt][2] = __expf(s[nt][2] - mn1);
            s[nt][3] = __expf(s[nt][3] - mn1);
            rs0 += s[nt][0] + s[nt][1];
            rs1 += s[nt][2] + s[nt][3];
            o[nt][0] *= al0; o[nt][1] *= al0;
            o[nt][2] *= al1; o[nt][3] *= al1;
        }
        rs0 += __shfl_xor_sync(0xffffffff, rs0, 1);
        rs0 += __shfl_xor_sync(0xffffffff, rs0, 2);
        rs1 += __shfl_xor_sync(0xffffffff, rs1, 1);
        rs1 += __shfl_xor_sync(0xffffffff, rs1, 2);
        l0 = l0 * al0 + rs0;
        l1 = l1 * al1 + rs1;

        // O += P @ V (3-pass split, pass-major within n2 pairs)
#pragma unroll
        for (int kc2 = 0; kc2 < 4; kc2++) {
            uint32_t aph[4], apl[4];
            pack_hl(s[2 * kc2][0], s[2 * kc2][1], aph[0], apl[0]);
            pack_hl(s[2 * kc2][2], s[2 * kc2][3], aph[1], apl[1]);
            pack_hl(s[2 * kc2 + 1][0], s[2 * kc2 + 1][1], aph[2], apl[2]);
            pack_hl(s[2 * kc2 + 1][2], s[2 * kc2 + 1][3], aph[3], apl[3]);
#pragma unroll
            for (int n2p = 0; n2p < 2; n2p++) {
                uint32_t vh[2][4], vl[2][4];
#pragma unroll
                for (int j = 0; j < 2; j++) {
                    const int n2 = n2p * 2 + j;
                    const uint32_t voff = (kc2 * 16 + v_k) * 144 + (n2 * 16 + v_n) * 2;
                    LDSM4T(vh[j][0], vh[j][1], vh[j][2], vh[j][3], sb + FK_H + 2 * 9216 + voff);
                    LDSM4T(vl[j][0], vl[j][1], vl[j][2], vl[j][3], sb + FK_H + 3 * 9216 + voff);
                }
#pragma unroll
                for (int j = 0; j < 2; j++) {
                    const int n2 = n2p * 2 + j;
                    MMA16816(o[n2 * 2 + 0], aph, vh[j][0], vh[j][1]);
                    MMA16816(o[n2 * 2 + 1], aph, vh[j][2], vh[j][3]);
                }
#pragma unroll
                for (int j = 0; j < 2; j++) {
                    const int n2 = n2p * 2 + j;
                    MMA16816(o[n2 * 2 + 0], aph, vl[j][0], vl[j][1]);
                    MMA16816(o[n2 * 2 + 1], aph, vl[j][2], vl[j][3]);
                }
#pragma unroll
                for (int j = 0; j < 2; j++) {
                    const int n2 = n2p * 2 + j;
                    MMA16816(o[n2 * 2 + 0], apl, vh[j][0], vh[j][1]);
                    MMA16816(o[n2 * 2 + 1], apl, vh[j][2], vh[j][3]);
                }
            }
        }
    }

    const float il0 = 1.0f / l0, il1 = 1.0f / l1;
    const int row0 = qbase + w * 16 + g;
#pragma unroll
    for (int nt = 0; nt < 8; nt++) {
        const int col = qh * 64 + nt * 8 + tg * 2;
        *(float2*)&O[(size_t)row0 * HID + col] = make_float2(o[nt][0] * il0, o[nt][1] * il0);
        *(float2*)&O[(size_t)(row0 + 8) * HID + col] = make_float2(o[nt][2] * il1, o[nt][3] * il1);
    }
}

// ---------------------------------------------------------------------------
extern "C" void kernel_launch(void* const* d_in, const int* in_sizes, int n_in,
                              void* d_out, int out_size) {
    const float* x        = (const float*)d_in[0];
    const float* q_proj   = (const float*)d_in[1];
    const float* k_proj   = (const float*)d_in[2];
    const float* v_proj   = (const float*)d_in[3];
    const float* o_proj   = (const float*)d_in[4];
    const float* inv_freq = (const float*)d_in[5];
    float* out = (float*)d_out;

    float *QKVb, *Ob;
    __nv_bfloat16 *Ahi, *Alo, *Whi, *Wlo, *Khi, *Klo, *Vhi, *Vlo;
    cudaGetSymbolAddress((void**)&QKVb, g_QKV);
    cudaGetSymbolAddress((void**)&Ob, g_O);
    cudaGetSymbolAddress((void**)&Ahi, g_Ahi);
    cudaGetSymbolAddress((void**)&Alo, g_Alo);
    cudaGetSymbolAddress((void**)&Whi, g_Whi);
    cudaGetSymbolAddress((void**)&Wlo, g_Wlo);
    cudaGetSymbolAddress((void**)&Khi, g_Khi);
    cudaGetSymbolAddress((void**)&Klo, g_Klo);
    cudaGetSymbolAddress((void**)&Vhi, g_Vhi);
    cudaGetSymbolAddress((void**)&Vlo, g_Vlo);

    cudaFuncSetAttribute(gemm_mma, cudaFuncAttributeMaxDynamicSharedMemorySize, G_SMEM);
    cudaFuncSetAttribute(flash_mma, cudaFuncAttributeMaxDynamicSharedMemorySize, F_SMEM);

    const int convBlocks = (SEQ * HID / 4) / 256;

    // x -> bf16 hi/lo
    convert_hl<<<convBlocks, 256>>>(x, Ahi, Alo);

    // transpose all three projection weights into one [3072, 2048] buffer
    transpose_hl<<<dim3(HID / 32, HID / 32), 256>>>(q_proj, Whi, Wlo, HID, HID);
    transpose_hl<<<dim3(KVD / 32, HID / 32), 256>>>(k_proj, Whi + (size_t)HID * HID,
                                                    Wlo + (size_t)HID * HID, HID, KVD);
    transpose_hl<<<dim3(KVD / 32, HID / 32), 256>>>(v_proj, Whi + (size_t)(HID + KVD) * HID,
                                                    Wlo + (size_t)(HID + KVD) * HID, HID, KVD);

    // fused QKV projection: [SEQ, 3072]
    gemm_mma<<<dim3(QKVN / 128, SEQ / 128), 256, G_SMEM>>>(Ahi, Alo, Whi, Wlo, QKVb,
                                                           SEQ, QKVN, HID);

    // RoPE + split (Q pre-scaled); V split
    rope_conv<<<SEQ * NQH / 8, 256>>>(QKVb, Ahi, Alo, inv_freq, NQH, 0.125f, QKVN, 0);
    rope_conv<<<SEQ * NKH / 8, 256>>>(QKVb, Khi, Klo, inv_freq, NKH, 1.0f, QKVN, HID);
    convert_hl_strided<<<(SEQ * KVD / 4) / 256, 256>>>(QKVb, Vhi, Vlo, QKVN, HID + KVD, KVD);

    // tensor-core flash attention
    flash_mma<<<dim3(SEQ / 128, NQH), 256, F_SMEM>>>(Ahi, Alo, Khi, Klo, Vhi, Vlo, Ob);

    // out = O @ o_proj
    convert_hl<<<convBlocks, 256>>>(Ob, Ahi, Alo);
    transpose_hl<<<dim3(HID / 32, HID / 32), 256>>>(o_proj, Whi, Wlo, HID, HID);
    gemm_mma<<<dim3(HID / 128, SEQ / 128), 256, G_SMEM>>>(Ahi, Alo, Whi, Wlo, out, SEQ, HID, HID);
}

// round 6
// speedup vs baseline: 3.1666x; 1.0054x over previous
#include <cuda_runtime.h>
#include <cuda_bf16.h>
#include <math.h>
#include <cstdint>

#define SEQ 2048
#define HID 2048
#define KVD 512
#define QKVN 3072
#define WROWS 5120
#define NQH 32
#define NKH 8

// ---------------- scratch (no allocations allowed) ----------------
__device__ float g_QKV[SEQ * QKVN];
__device__ __nv_bfloat16 g_Ahi[SEQ * HID];
__device__ __nv_bfloat16 g_Alo[SEQ * HID];
__device__ __nv_bfloat16 g_Ohi[SEQ * HID];
__device__ __nv_bfloat16 g_Olo[SEQ * HID];
__device__ __nv_bfloat16 g_Whi[WROWS * HID];   // transposed weights [N,K]: q|k|v|o
__device__ __nv_bfloat16 g_Wlo[WROWS * HID];
__device__ __nv_bfloat16 g_Khi[SEQ * KVD];
__device__ __nv_bfloat16 g_Klo[SEQ * KVD];
__device__ __nv_bfloat16 g_Vhi[SEQ * KVD];
__device__ __nv_bfloat16 g_Vlo[SEQ * KVD];

// ---------------- helpers ----------------
__device__ __forceinline__ uint32_t smem_u32(const void* p) {
    uint32_t a;
    asm("{ .reg .u64 t; cvta.to.shared.u64 t, %1; cvt.u32.u64 %0, t; }" : "=r"(a) : "l"(p));
    return a;
}

#define LDSM4(r0, r1, r2, r3, addr) \
    asm volatile("ldmatrix.sync.aligned.m8n8.x4.shared.b16 {%0,%1,%2,%3}, [%4];" \
        : "=r"(r0), "=r"(r1), "=r"(r2), "=r"(r3) : "r"(addr))

#define LDSM4T(r0, r1, r2, r3, addr) \
    asm volatile("ldmatrix.sync.aligned.m8n8.x4.trans.shared.b16 {%0,%1,%2,%3}, [%4];" \
        : "=r"(r0), "=r"(r1), "=r"(r2), "=r"(r3) : "r"(addr))

#define MMA16816(d, a, b0, b1) \
    asm volatile("mma.sync.aligned.m16n8k16.row.col.f32.bf16.bf16.f32 " \
        "{%0,%1,%2,%3},{%4,%5,%6,%7},{%8,%9},{%0,%1,%2,%3};" \
        : "+f"((d)[0]), "+f"((d)[1]), "+f"((d)[2]), "+f"((d)[3]) \
        : "r"((a)[0]), "r"((a)[1]), "r"((a)[2]), "r"((a)[3]), "r"(b0), "r"(b1))

#define CP_ASYNC16(dst, src) \
    asm volatile("cp.async.cg.shared.global [%0], [%1], 16;" :: "r"(dst), "l"(src))
#define CP_COMMIT() asm volatile("cp.async.commit_group;" ::: "memory")
#define CP_WAIT0()  asm volatile("cp.async.wait_group 0;" ::: "memory")
#define CP_WAIT1()  asm volatile("cp.async.wait_group 1;" ::: "memory")

// ---------------- split-convert kernels ----------------
__device__ __forceinline__ uint32_t pack_bf2(__nv_bfloat16 a, __nv_bfloat16 b) {
    __nv_bfloat162 t(a, b);
    return *reinterpret_cast<uint32_t*>(&t);
}

__global__ __launch_bounds__(256) void convert_hl(const float* __restrict__ X,
                                                  __nv_bfloat16* __restrict__ hi,
                                                  __nv_bfloat16* __restrict__ lo) {
    int i = blockIdx.x * 256 + threadIdx.x;
    float4 v = *(const float4*)(X + (size_t)i * 4);
    __nv_bfloat16 h0 = __float2bfloat16_rn(v.x), h1 = __float2bfloat16_rn(v.y);
    __nv_bfloat16 h2 = __float2bfloat16_rn(v.z), h3 = __float2bfloat16_rn(v.w);
    __nv_bfloat16 l0 = __float2bfloat16_rn(v.x - __bfloat162float(h0));
    __nv_bfloat16 l1 = __float2bfloat16_rn(v.y - __bfloat162float(h1));
    __nv_bfloat16 l2 = __float2bfloat16_rn(v.z - __bfloat162float(h2));
    __nv_bfloat16 l3 = __float2bfloat16_rn(v.w - __bfloat162float(h3));
    *(uint2*)(hi + (size_t)i * 4) = make_uint2(pack_bf2(h0, h1), pack_bf2(h2, h3));
    *(uint2*)(lo + (size_t)i * 4) = make_uint2(pack_bf2(l0, l1), pack_bf2(l2, l3));
}

__global__ __launch_bounds__(256) void convert_hl_strided(const float* __restrict__ X,
                                                          __nv_bfloat16* __restrict__ hi,
                                                          __nv_bfloat16* __restrict__ lo,
                                                          int ld, int col0, int cols) {
    int i = blockIdx.x * 256 + threadIdx.x;
    int r = i / (cols / 4), q = i % (cols / 4);
    float4 v = *(const float4*)(X + (size_t)r * ld + col0 + q * 4);
    __nv_bfloat16 h0 = __float2bfloat16_rn(v.x), h1 = __float2bfloat16_rn(v.y);
    __nv_bfloat16 h2 = __float2bfloat16_rn(v.z), h3 = __float2bfloat16_rn(v.w);
    __nv_bfloat16 l0 = __float2bfloat16_rn(v.x - __bfloat162float(h0));
    __nv_bfloat16 l1 = __float2bfloat16_rn(v.y - __bfloat162float(h1));
    __nv_bfloat16 l2 = __float2bfloat16_rn(v.z - __bfloat162float(h2));
    __nv_bfloat16 l3 = __float2bfloat16_rn(v.w - __bfloat162float(h3));
    size_t o = (size_t)r * cols + q * 4;
    *(uint2*)(hi + o) = make_uint2(pack_bf2(h0, h1), pack_bf2(h2, h3));
    *(uint2*)(lo + o) = make_uint2(pack_bf2(l0, l1), pack_bf2(l2, l3));
}

// fused transpose of all 4 weight matrices into [WROWS, HID] hi/lo
__global__ __launch_bounds__(256) void transpose_all(const float* __restrict__ Wq,
                                                     const float* __restrict__ Wk,
                                                     const float* __restrict__ Wv,
                                                     const float* __restrict__ Wo,
                                                     __nv_bfloat16* __restrict__ thi,
                                                     __nv_bfloat16* __restrict__ tlo) {
    __shared__ float t[32][33];
    int bx = blockIdx.x;
    const float* W;
    int N, nblk, dstoff;
    if (bx < 64)       { W = Wq; N = HID; nblk = bx;      dstoff = 0; }
    else if (bx < 80)  { W = Wk; N = KVD; nblk = bx - 64; dstoff = HID; }
    else if (bx < 96)  { W = Wv; N = KVD; nblk = bx - 80; dstoff = HID + KVD; }
    else               { W = Wo; N = HID; nblk = bx - 96; dstoff = QKVN; }
    int tx = threadIdx.x & 31, ty = threadIdx.x >> 5;
    int k0 = blockIdx.y * 32, n0 = nblk * 32;
#pragma unroll
    for (int i = 0; i < 4; i++)
        t[ty + i * 8][tx] = W[(size_t)(k0 + ty + i * 8) * N + n0 + tx];
    __syncthreads();
#pragma unroll
    for (int i = 0; i < 4; i++) {
        float v = t[tx][ty + i * 8];
        __nv_bfloat16 h = __float2bfloat16_rn(v);
        __nv_bfloat16 l = __float2bfloat16_rn(v - __bfloat162float(h));
        size_t o = (size_t)(dstoff + n0 + ty + i * 8) * HID + k0 + tx;
        thi[o] = h;
        tlo[o] = l;
    }
}

// RoPE + scale + hi/lo split (warp per (s,h)); reads strided slab, writes packed
__global__ __launch_bounds__(256) void rope_conv(const float* __restrict__ X,
                                                 __nv_bfloat16* __restrict__ hi,
                                                 __nv_bfloat16* __restrict__ lo,
                                                 const float* __restrict__ inv_freq,
                                                 int heads, float scale, int ld, int col0) {
    int idx = blockIdx.x * 8 + (threadIdx.x >> 5);
    int j = threadIdx.x & 31;
    int s = idx / heads;
    int h = idx - s * heads;
    const float* p = X + (size_t)s * ld + col0 + h * 64;
    float angle = (float)s * inv_freq[j];
    float sn = sinf(angle), cs = cosf(angle);
    float a = p[j], b = p[32 + j];
    float r0 = (a * cs + b * sn) * scale;
    float r1 = (a * sn - b * cs) * scale;
    size_t o = (size_t)s * heads * 64 + h * 64;
    __nv_bfloat16 h0 = __float2bfloat16_rn(r0);
    __nv_bfloat16 h1 = __float2bfloat16_rn(r1);
    hi[o + j] = h0;
    hi[o + 32 + j] = h1;
    lo[o + j] = __float2bfloat16_rn(r0 - __bfloat162float(h0));
    lo[o + 32 + j] = __float2bfloat16_rn(r1 - __bfloat162float(h1));
}

// ---------------- mma.sync GEMM, pass-major MMA ordering ----------------
#define TILE_B 10240
#define BUF_B  40960
#define G_SMEM (2 * BUF_B)

__device__ __forceinline__ void tile_async(uint32_t dst, const __nv_bfloat16* src,
                                           int ldk, int tid) {
#pragma unroll
    for (int t = 0; t < 2; t++) {
        int i = tid + t * 256;
        int r = i >> 2, q = i & 3;
        const void* g = src + (size_t)r * ldk + q * 8;
        CP_ASYNC16(dst + r * 80 + q * 16, g);
    }
}

__global__ __launch_bounds__(256, 1) void gemm_mma(
    const __nv_bfloat16* __restrict__ Ahi, const __nv_bfloat16* __restrict__ Alo,
    const __nv_bfloat16* __restrict__ Bhi, const __nv_bfloat16* __restrict__ Blo,
    float* __restrict__ C, int M, int N, int K) {
    extern __shared__ char smem[];
    const uint32_t sb = smem_u32(smem);
    const int tid = threadIdx.x;
    const int w = tid >> 5;
    const int lane = tid & 31;
    const int wm = (w & 1) * 64;
    const int wn = (w >> 1) * 32;
    const int m0 = blockIdx.y * 128;
    const int n0 = blockIdx.x * 128;

    const int a_row = lane & 15;
    const int a_kh = (lane >> 4) & 1;
    const int b_n = (lane & 7) + ((lane >> 4) << 3);
    const int b_kh = (lane >> 3) & 1;

    float acc[4][4][4];
#pragma unroll
    for (int i = 0; i < 4; i++)
#pragma unroll
        for (int j = 0; j < 4; j++)
#pragma unroll
            for (int r = 0; r < 4; r++) acc[i][j][r] = 0.f;

    const int NC = K >> 5;
    {
        const size_t ak = (size_t)m0 * K;
        const size_t bk = (size_t)n0 * K;
        tile_async(sb,              Ahi + ak, K, tid);
        tile_async(sb + TILE_B,     Alo + ak, K, tid);
        tile_async(sb + 2 * TILE_B, Bhi + bk, K, tid);
        tile_async(sb + 3 * TILE_B, Blo + bk, K, tid);
        CP_COMMIT();
    }

    for (int c = 0; c < NC; c++) {
        CP_WAIT0();
        __syncthreads();
        if (c + 1 < NC) {
            const uint32_t nb = sb + ((c + 1) & 1) * BUF_B;
            const size_t ak = (size_t)m0 * K + (size_t)(c + 1) * 32;
            const size_t bk = (size_t)n0 * K + (size_t)(c + 1) * 32;
            tile_async(nb,              Ahi + ak, K, tid);
            tile_async(nb + TILE_B,     Alo + ak, K, tid);
            tile_async(nb + 2 * TILE_B, Bhi + bk, K, tid);
            tile_async(nb + 3 * TILE_B, Blo + bk, K, tid);
            CP_COMMIT();
        }
        const uint32_t base = sb + (c & 1) * BUF_B;

#pragma unroll
        for (int ks = 0; ks < 32; ks += 16) {
            uint32_t ah[4][4], al[4][4], bh[2][4], bl[2][4];
            const uint32_t aoff = (uint32_t)((wm + a_row) * 80 + (ks + a_kh * 8) * 2);
            const uint32_t boff = (uint32_t)((wn + b_n) * 80 + (ks + b_kh * 8) * 2);
#pragma unroll
            for (int mt = 0; mt < 4; mt++) {
                LDSM4(ah[mt][0], ah[mt][1], ah[mt][2], ah[mt][3],
                      base + aoff + mt * 16 * 80);
                LDSM4(al[mt][0], al[mt][1], al[mt][2], al[mt][3],
                      base + TILE_B + aoff + mt * 16 * 80);
            }
#pragma unroll
            for (int np = 0; np < 2; np++) {
                LDSM4(bh[np][0], bh[np][1], bh[np][2], bh[np][3],
                      base + 2 * TILE_B + boff + np * 16 * 80);
                LDSM4(bl[np][0], bl[np][1], bl[np][2], bl[np][3],
                      base + 3 * TILE_B + boff + np * 16 * 80);
            }
#pragma unroll
            for (int mt = 0; mt < 4; mt++)
#pragma unroll
                for (int np = 0; np < 2; np++) {
                    MMA16816(acc[mt][np * 2 + 0], ah[mt], bh[np][0], bh[np][1]);
                    MMA16816(acc[mt][np * 2 + 1], ah[mt], bh[np][2], bh[np][3]);
                }
#pragma unroll
            for (int mt = 0; mt < 4; mt++)
#pragma unroll
                for (int np = 0; np < 2; np++) {
                    MMA16816(acc[mt][np * 2 + 0], ah[mt], bl[np][0], bl[np][1]);
                    MMA16816(acc[mt][np * 2 + 1], ah[mt], bl[np][2], bl[np][3]);
                }
#pragma unroll
            for (int mt = 0; mt < 4; mt++)
#pragma unroll
                for (int np = 0; np < 2; np++) {
                    MMA16816(acc[mt][np * 2 + 0], al[mt], bh[np][0], bh[np][1]);
                    MMA16816(acc[mt][np * 2 + 1], al[mt], bh[np][2], bh[np][3]);
                }
        }
    }

    const int g = lane >> 2, c2 = lane & 3;
#pragma unroll
    for (int mt = 0; mt < 4; mt++) {
        const int row = m0 + wm + mt * 16 + g;
#pragma unroll
        for (int nt = 0; nt < 4; nt++) {
            const int col = n0 + wn + nt * 8 + c2 * 2;
            *(float2*)&C[(size_t)row * N + col] =
                make_float2(acc[mt][nt][0], acc[mt][nt][1]);
            *(float2*)&C[(size_t)(row + 8) * N + col] =
                make_float2(acc[mt][nt][2], acc[mt][nt][3]);
        }
    }
}

// ---------------- tensor-core flash attention (double-buffered K/V) ----------------
#define FQ_H 0
#define FQ_L 18432
#define FKV  36864
#define FKV_STRIDE 36864
#define F_SMEM 110592

__device__ __forceinline__ void pack_hl(float p0, float p1, uint32_t& hi, uint32_t& lo) {
    __nv_bfloat162 h = __floats2bfloat162_rn(p0, p1);
    hi = *reinterpret_cast<uint32_t*>(&h);
    __nv_bfloat162 l = __floats2bfloat162_rn(p0 - __bfloat162float(h.x),
                                             p1 - __bfloat162float(h.y));
    lo = *reinterpret_cast<uint32_t*>(&l);
}

__global__ __launch_bounds__(256, 2) void flash_mma(
    const __nv_bfloat16* __restrict__ Qhi, const __nv_bfloat16* __restrict__ Qlo,
    const __nv_bfloat16* __restrict__ Khi, const __nv_bfloat16* __restrict__ Klo,
    const __nv_bfloat16* __restrict__ Vhi, const __nv_bfloat16* __restrict__ Vlo,
    __nv_bfloat16* __restrict__ Ohi, __nv_bfloat16* __restrict__ Olo) {
    extern __shared__ char smem[];
    const uint32_t sb = smem_u32(smem);
    const int tid = threadIdx.x;
    const int lane = tid & 31;
    const int w = tid >> 5;
    const int ib = gridDim.x - 1 - blockIdx.x;
    const int qh = blockIdx.y;
    const int kh = qh >> 2;
    const int qbase = ib * 128;

    // Q tile (group 0)
#pragma unroll
    for (int i = 0; i < 8; i++) {
        int idx = tid + i * 256;
        int sub = idx >> 10, r = (idx >> 3) & 127, q = idx & 7;
        const __nv_bfloat16* src = (sub ? Qlo : Qhi) + (size_t)(qbase + r) * HID + qh * 64 + q * 8;
        CP_ASYNC16(sb + sub * 18432 + r * 144 + q * 16, src);
    }
    CP_COMMIT();

    // KV chunk 0 -> buf 0 (group 1)
#pragma unroll
    for (int i = 0; i < 8; i++) {
        int idx = tid + i * 256;
        int sub = idx >> 9, r = (idx >> 3) & 63, q = idx & 7;
        const __nv_bfloat16* base = (sub == 0) ? Khi : (sub == 1) ? Klo
                                   : (sub == 2) ? Vhi : Vlo;
        const __nv_bfloat16* src = base + (size_t)r * KVD + kh * 64 + q * 8;
        CP_ASYNC16(sb + FKV + sub * 9216 + r * 144 + q * 16, src);
    }
    CP_COMMIT();

    const int a_row = lane & 15, a_kh = lane >> 4;
    const int b_n = (lane & 7) + ((lane >> 4) << 3), b_kh = (lane >> 3) & 1;
    const int v_k = (lane & 7) + ((lane >> 3) & 1) * 8, v_n = (lane >> 4) * 8;
    const int g = lane >> 2, tg = lane & 3;

    float o[8][4];
#pragma unroll
    for (int nt = 0; nt < 8; nt++)
#pragma unroll
        for (int r = 0; r < 4; r++) o[nt][r] = 0.f;
    float m0 = -1e30f, m1 = -1e30f, l0 = 0.f, l1 = 0.f;

    const int jbmax = 2 * ib + 1;
    for (int jb = 0; jb <= jbmax; jb++) {
        const uint32_t kvb = sb + FKV + (jb & 1) * FKV_STRIDE;
        __syncthreads();  // previous compute on the other buffer is done
        if (jb < jbmax) {
            const uint32_t nb = sb + FKV + ((jb + 1) & 1) * FKV_STRIDE;
#pragma unroll
            for (int i = 0; i < 8; i++) {
                int idx = tid + i * 256;
                int sub = idx >> 9, r = (idx >> 3) & 63, q = idx & 7;
                const __nv_bfloat16* base = (sub == 0) ? Khi : (sub == 1) ? Klo
                                           : (sub == 2) ? Vhi : Vlo;
                const __nv_bfloat16* src = base + (size_t)((jb + 1) * 64 + r) * KVD + kh * 64 + q * 8;
                CP_ASYNC16(nb + sub * 9216 + r * 144 + q * 16, src);
            }
            CP_COMMIT();
            CP_WAIT1();
        } else {
            CP_WAIT0();
        }
        __syncthreads();

        // S = Q K^T (3-pass split, pass-major)
        float s[8][4];
#pragma unroll
        for (int nt = 0; nt < 8; nt++)
#pragma unroll
            for (int r = 0; r < 4; r++) s[nt][r] = 0.f;
#pragma unroll
        for (int kc = 0; kc < 4; kc++) {
            uint32_t ah[4], al[4];
            const uint32_t aoff = (w * 16 + a_row) * 144 + (kc * 16 + a_kh * 8) * 2;
            LDSM4(ah[0], ah[1], ah[2], ah[3], sb + FQ_H + aoff);
            LDSM4(al[0], al[1], al[2], al[3], sb + FQ_L + aoff);
#pragma unroll
            for (int n2p = 0; n2p < 2; n2p++) {
                uint32_t bh[2][4], bl[2][4];
#pragma unroll
                for (int j = 0; j < 2; j++) {
                    const int n2 = n2p * 2 + j;
                    const uint32_t boff = (n2 * 16 + b_n) * 144 + (kc * 16 + b_kh * 8) * 2;
                    LDSM4(bh[j][0], bh[j][1], bh[j][2], bh[j][3], kvb + boff);
                    LDSM4(bl[j][0], bl[j][1], bl[j][2], bl[j][3], kvb + 9216 + boff);
                }
#pragma unroll
                for (int j = 0; j < 2; j++) {
                    const int n2 = n2p * 2 + j;
                    MMA16816(s[n2 * 2 + 0], ah, bh[j][0], bh[j][1]);
                    MMA16816(s[n2 * 2 + 1], ah, bh[j][2], bh[j][3]);
                }
#pragma unroll
                for (int j = 0; j < 2; j++) {
                    const int n2 = n2p * 2 + j;
                    MMA16816(s[n2 * 2 + 0], ah, bl[j][0], bl[j][1]);
                    MMA16816(s[n2 * 2 + 1], ah, bl[j][2], bl[j][3]);
                }
#pragma unroll
                for (int j = 0; j < 2; j++) {
                    const int n2 = n2p * 2 + j;
                    MMA16816(s[n2 * 2 + 0], al, bh[j][0], bh[j][1]);
                    MMA16816(s[n2 * 2 + 1], al, bh[j][2], bh[j][3]);
                }
            }
        }

        if (jb >= 2 * ib) {
            const int row0 = qbase + w * 16 + g;
            const int row1 = row0 + 8;
#pragma unroll
            for (int nt = 0; nt < 8; nt++) {
                const int col = jb * 64 + nt * 8 + tg * 2;
                if (col > row0) s[nt][0] = -1e30f;
                if (col + 1 > row0) s[nt][1] = -1e30f;
                if (col > row1) s[nt][2] = -1e30f;
                if (col + 1 > row1) s[nt][3] = -1e30f;
            }
        }

        float mx0 = -1e30f, mx1 = -1e30f;
#pragma unroll
        for (int nt = 0; nt < 8; nt++) {
            mx0 = fmaxf(mx0, fmaxf(s[nt][0], s[nt][1]));
            mx1 = fmaxf(mx1, fmaxf(s[nt][2], s[nt][3]));
        }
        mx0 = fmaxf(mx0, __shfl_xor_sync(0xffffffff, mx0, 1));
        mx0 = fmaxf(mx0, __shfl_xor_sync(0xffffffff, mx0, 2));
        mx1 = fmaxf(mx1, __shfl_xor_sync(0xffffffff, mx1, 1));
        mx1 = fmaxf(mx1, __shfl_xor_sync(0xffffffff, mx1, 2));
        const float mn0 = fmaxf(m0, mx0), mn1 = fmaxf(m1, mx1);
        const float al0 = __expf(m0 - mn0), al1 = __expf(m1 - mn1);
        m0 = mn0; m1 = mn1;

        float rs0 = 0.f, rs1 = 0.f;
#pragma unroll
        for (int nt = 0; nt < 8; nt++) {
            s[nt][0] = __expf(s[nt][0] - mn0);
            s[nt][1] = __expf(s[nt][1] - mn0);
            s[nt][2] = __expf(s[nt][2] - mn1);
            s[nt][3] = __expf(s[nt][3] - mn1);
            rs0 += s[nt][0] + s[nt][1];
            rs1 += s[nt][2] + s[nt][3];
            o[nt][0] *= al0; o[nt][1] *= al0;
            o[nt][2] *= al1; o[nt][3] *= al1;
        }
        rs0 += __shfl_xor_sync(0xffffffff, rs0, 1);
        rs0 += __shfl_xor_sync(0xffffffff, rs0, 2);
        rs1 += __shfl_xor_sync(0xffffffff, rs1, 1);
        rs1 += __shfl_xor_sync(0xffffffff, rs1, 2);
        l0 = l0 * al0 + rs0;
        l1 = l1 * al1 + rs1;

        // O += P @ V (3-pass split, pass-major)
#pragma unroll
        for (int kc2 = 0; kc2 < 4; kc2++) {
            uint32_t aph[4], apl[4];
            pack_hl(s[2 * kc2][0], s[2 * kc2][1], aph[0], apl[0]);
            pack_hl(s[2 * kc2][2], s[2 * kc2][3], aph[1], apl[1]);
            pack_hl(s[2 * kc2 + 1][0], s[2 * kc2 + 1][1], aph[2], apl[2]);
            pack_hl(s[2 * kc2 + 1][2], s[2 * kc2 + 1][3], aph[3], apl[3]);
#pragma unroll
            for (int n2p = 0; n2p < 2; n2p++) {
                uint32_t vh[2][4], vl[2][4];
#pragma unroll
                for (int j = 0; j < 2; j++) {
                    const int n2 = n2p * 2 + j;
                    const uint32_t voff = (kc2 * 16 + v_k) * 144 + (n2 * 16 + v_n) * 2;
                    LDSM4T(vh[j][0], vh[j][1], vh[j][2], vh[j][3], kvb + 2 * 9216 + voff);
                    LDSM4T(vl[j][0], vl[j][1], vl[j][2], vl[j][3], kvb + 3 * 9216 + voff);
                }
#pragma unroll
                for (int j = 0; j < 2; j++) {
                    const int n2 = n2p * 2 + j;
                    MMA16816(o[n2 * 2 + 0], aph, vh[j][0], vh[j][1]);
                    MMA16816(o[n2 * 2 + 1], aph, vh[j][2], vh[j][3]);
                }
#pragma unroll
                for (int j = 0; j < 2; j++) {
                    const int n2 = n2p * 2 + j;
                    MMA16816(o[n2 * 2 + 0], aph, vl[j][0], vl[j][1]);
                    MMA16816(o[n2 * 2 + 1], aph, vl[j][2], vl[j][3]);
                }
#pragma unroll
                for (int j = 0; j < 2; j++) {
                    const int n2 = n2p * 2 + j;
                    MMA16816(o[n2 * 2 + 0], apl, vh[j][0], vh[j][1]);
                    MMA16816(o[n2 * 2 + 1], apl, vh[j][2], vh[j][3]);
                }
            }
        }
    }

    // epilogue: write bf16 hi/lo directly (feeds o_proj GEMM)
    const float il0 = 1.0f / l0, il1 = 1.0f / l1;
    const int row0 = qbase + w * 16 + g;
#pragma unroll
    for (int nt = 0; nt < 8; nt++) {
        const int col = qh * 64 + nt * 8 + tg * 2;
        uint32_t h, l;
        pack_hl(o[nt][0] * il0, o[nt][1] * il0, h, l);
        *(uint32_t*)&Ohi[(size_t)row0 * HID + col] = h;
        *(uint32_t*)&Olo[(size_t)row0 * HID + col] = l;
        pack_hl(o[nt][2] * il1, o[nt][3] * il1, h, l);
        *(uint32_t*)&Ohi[(size_t)(row0 + 8) * HID + col] = h;
        *(uint32_t*)&Olo[(size_t)(row0 + 8) * HID + col] = l;
    }
}

// ---------------------------------------------------------------------------
extern "C" void kernel_launch(void* const* d_in, const int* in_sizes, int n_in,
                              void* d_out, int out_size) {
    const float* x        = (const float*)d_in[0];
    const float* q_proj   = (const float*)d_in[1];
    const float* k_proj   = (const float*)d_in[2];
    const float* v_proj   = (const float*)d_in[3];
    const float* o_proj   = (const float*)d_in[4];
    const float* inv_freq = (const float*)d_in[5];
    float* out = (float*)d_out;

    float *QKVb;
    __nv_bfloat16 *Ahi, *Alo, *Ohi, *Olo, *Whi, *Wlo, *Khi, *Klo, *Vhi, *Vlo;
    cudaGetSymbolAddress((void**)&QKVb, g_QKV);
    cudaGetSymbolAddress((void**)&Ahi, g_Ahi);
    cudaGetSymbolAddress((void**)&Alo, g_Alo);
    cudaGetSymbolAddress((void**)&Ohi, g_Ohi);
    cudaGetSymbolAddress((void**)&Olo, g_Olo);
    cudaGetSymbolAddress((void**)&Whi, g_Whi);
    cudaGetSymbolAddress((void**)&Wlo, g_Wlo);
    cudaGetSymbolAddress((void**)&Khi, g_Khi);
    cudaGetSymbolAddress((void**)&Klo, g_Klo);
    cudaGetSymbolAddress((void**)&Vhi, g_Vhi);
    cudaGetSymbolAddress((void**)&Vlo, g_Vlo);

    cudaFuncSetAttribute(gemm_mma, cudaFuncAttributeMaxDynamicSharedMemorySize, G_SMEM);
    cudaFuncSetAttribute(flash_mma, cudaFuncAttributeMaxDynamicSharedMemorySize, F_SMEM);

    const int convBlocks = (SEQ * HID / 4) / 256;

    // x -> bf16 hi/lo ; all 4 weights -> transposed hi/lo (one launch)
    convert_hl<<<convBlocks, 256>>>(x, Ahi, Alo);
    transpose_all<<<dim3(160, HID / 32), 256>>>(q_proj, k_proj, v_proj, o_proj, Whi, Wlo);

    // fused QKV projection: [SEQ, 3072]
    gemm_mma<<<dim3(QKVN / 128, SEQ / 128), 256, G_SMEM>>>(Ahi, Alo, Whi, Wlo, QKVb,
                                                           SEQ, QKVN, HID);

    // RoPE + split (Q pre-scaled); V split
    rope_conv<<<SEQ * NQH / 8, 256>>>(QKVb, Ahi, Alo, inv_freq, NQH, 0.125f, QKVN, 0);
    rope_conv<<<SEQ * NKH / 8, 256>>>(QKVb, Khi, Klo, inv_freq, NKH, 1.0f, QKVN, HID);
    convert_hl_strided<<<(SEQ * KVD / 4) / 256, 256>>>(QKVb, Vhi, Vlo, QKVN, HID + KVD, KVD);

    // tensor-core flash attention (writes bf16 hi/lo directly)
    flash_mma<<<dim3(SEQ / 128, NQH), 256, F_SMEM>>>(Ahi, Alo, Khi, Klo, Vhi, Vlo, Ohi, Olo);

    // out = O @ o_proj
    gemm_mma<<<dim3(HID / 128, SEQ / 128), 256, G_SMEM>>>(Ohi, Olo, Whi + (size_t)QKVN * HID,
                                                          Wlo + (size_t)QKVN * HID, out,
                                                          SEQ, HID, HID);
}

// round 7
// speedup vs baseline: 3.7008x; 1.1687x over previous
#include <cuda_runtime.h>
#include <cuda_bf16.h>
#include <cuda_fp16.h>
#include <math.h>
#include <cstdint>

#define SEQ 2048
#define HID 2048
#define KVD 512
#define QKVN 3072
#define NQH 32
#define NKH 8

// ---------------- scratch (no allocations allowed) ----------------
__device__ float g_QKV[SEQ * QKVN];
__device__ __nv_bfloat16 g_Ahi[SEQ * HID];
__device__ __nv_bfloat16 g_Alo[SEQ * HID];
__device__ __half g_Ohf[SEQ * HID];
__device__ __half g_Olf[SEQ * HID];
__device__ __nv_bfloat16 g_Whi[QKVN * HID];   // transposed q|k|v weights [N,K] bf16
__device__ __nv_bfloat16 g_Wlo[QKVN * HID];
__device__ __half g_Woh[HID * HID];           // transposed o weights, fp16 hi only
__device__ __nv_bfloat16 g_Khi[SEQ * KVD];
__device__ __nv_bfloat16 g_Klo[SEQ * KVD];
__device__ __half g_Vh[SEQ * KVD];            // V fp16 hi only
__device__ float2 g_sc[SEQ * 32];             // sincos LUT

// ---------------- helpers ----------------
__device__ __forceinline__ uint32_t smem_u32(const void* p) {
    uint32_t a;
    asm("{ .reg .u64 t; cvta.to.shared.u64 t, %1; cvt.u32.u64 %0, t; }" : "=r"(a) : "l"(p));
    return a;
}

#define LDSM4(r0, r1, r2, r3, addr) \
    asm volatile("ldmatrix.sync.aligned.m8n8.x4.shared.b16 {%0,%1,%2,%3}, [%4];" \
        : "=r"(r0), "=r"(r1), "=r"(r2), "=r"(r3) : "r"(addr))

#define LDSM4T(r0, r1, r2, r3, addr) \
    asm volatile("ldmatrix.sync.aligned.m8n8.x4.trans.shared.b16 {%0,%1,%2,%3}, [%4];" \
        : "=r"(r0), "=r"(r1), "=r"(r2), "=r"(r3) : "r"(addr))

#define MMA16816(d, a, b0, b1) \
    asm volatile("mma.sync.aligned.m16n8k16.row.col.f32.bf16.bf16.f32 " \
        "{%0,%1,%2,%3},{%4,%5,%6,%7},{%8,%9},{%0,%1,%2,%3};" \
        : "+f"((d)[0]), "+f"((d)[1]), "+f"((d)[2]), "+f"((d)[3]) \
        : "r"((a)[0]), "r"((a)[1]), "r"((a)[2]), "r"((a)[3]), "r"(b0), "r"(b1))

#define MMA16816F(d, a, b0, b1) \
    asm volatile("mma.sync.aligned.m16n8k16.row.col.f32.f16.f16.f32 " \
        "{%0,%1,%2,%3},{%4,%5,%6,%7},{%8,%9},{%0,%1,%2,%3};" \
        : "+f"((d)[0]), "+f"((d)[1]), "+f"((d)[2]), "+f"((d)[3]) \
        : "r"((a)[0]), "r"((a)[1]), "r"((a)[2]), "r"((a)[3]), "r"(b0), "r"(b1))

#define CP_ASYNC16(dst, src) \
    asm volatile("cp.async.cg.shared.global [%0], [%1], 16;" :: "r"(dst), "l"(src))
#define CP_COMMIT() asm volatile("cp.async.commit_group;" ::: "memory")
#define CP_WAIT0()  asm volatile("cp.async.wait_group 0;" ::: "memory")
#define CP_WAIT1()  asm volatile("cp.async.wait_group 1;" ::: "memory")

// ---------------- elementwise kernels ----------------
__device__ __forceinline__ uint32_t pack_bf2(__nv_bfloat16 a, __nv_bfloat16 b) {
    __nv_bfloat162 t(a, b);
    return *reinterpret_cast<uint32_t*>(&t);
}

__global__ __launch_bounds__(256) void convert_hl(const float* __restrict__ X,
                                                  __nv_bfloat16* __restrict__ hi,
                                                  __nv_bfloat16* __restrict__ lo) {
    int i = blockIdx.x * 256 + threadIdx.x;
    float4 v = *(const float4*)(X + (size_t)i * 4);
    __nv_bfloat16 h0 = __float2bfloat16_rn(v.x), h1 = __float2bfloat16_rn(v.y);
    __nv_bfloat16 h2 = __float2bfloat16_rn(v.z), h3 = __float2bfloat16_rn(v.w);
    __nv_bfloat16 l0 = __float2bfloat16_rn(v.x - __bfloat162float(h0));
    __nv_bfloat16 l1 = __float2bfloat16_rn(v.y - __bfloat162float(h1));
    __nv_bfloat16 l2 = __float2bfloat16_rn(v.z - __bfloat162float(h2));
    __nv_bfloat16 l3 = __float2bfloat16_rn(v.w - __bfloat162float(h3));
    *(uint2*)(hi + (size_t)i * 4) = make_uint2(pack_bf2(h0, h1), pack_bf2(h2, h3));
    *(uint2*)(lo + (size_t)i * 4) = make_uint2(pack_bf2(l0, l1), pack_bf2(l2, l3));
}

// strided fp32 -> fp16 (hi only) for V
__global__ __launch_bounds__(256) void convert_h16_strided(const float* __restrict__ X,
                                                           __half* __restrict__ h,
                                                           int ld, int col0, int cols) {
    int i = blockIdx.x * 256 + threadIdx.x;
    int r = i / (cols / 4), q = i % (cols / 4);
    float4 v = *(const float4*)(X + (size_t)r * ld + col0 + q * 4);
    __half2 a = __floats2half2_rn(v.x, v.y);
    __half2 b = __floats2half2_rn(v.z, v.w);
    *(uint2*)(h + (size_t)r * cols + q * 4) =
        make_uint2(*reinterpret_cast<uint32_t*>(&a), *reinterpret_cast<uint32_t*>(&b));
}

// fused transpose: q,k,v -> bf16 hi/lo into Whi/Wlo; o -> fp16 hi into Woh
__global__ __launch_bounds__(256) void transpose_all(const float* __restrict__ Wq,
                                                     const float* __restrict__ Wk,
                                                     const float* __restrict__ Wv,
                                                     const float* __restrict__ Wo,
                                                     __nv_bfloat16* __restrict__ thi,
                                                     __nv_bfloat16* __restrict__ tlo,
                                                     __half* __restrict__ toh) {
    __shared__ float t[32][33];
    int bx = blockIdx.x;
    const float* W;
    int N, nblk, dstoff;
    bool is_o = false;
    if (bx < 64)       { W = Wq; N = HID; nblk = bx;      dstoff = 0; }
    else if (bx < 80)  { W = Wk; N = KVD; nblk = bx - 64; dstoff = HID; }
    else if (bx < 96)  { W = Wv; N = KVD; nblk = bx - 80; dstoff = HID + KVD; }
    else               { W = Wo; N = HID; nblk = bx - 96; dstoff = 0; is_o = true; }
    int tx = threadIdx.x & 31, ty = threadIdx.x >> 5;
    int k0 = blockIdx.y * 32, n0 = nblk * 32;
#pragma unroll
    for (int i = 0; i < 4; i++)
        t[ty + i * 8][tx] = W[(size_t)(k0 + ty + i * 8) * N + n0 + tx];
    __syncthreads();
#pragma unroll
    for (int i = 0; i < 4; i++) {
        float v = t[tx][ty + i * 8];
        size_t o = (size_t)(dstoff + n0 + ty + i * 8) * HID + k0 + tx;
        if (is_o) {
            toh[o] = __float2half_rn(v);
        } else {
            __nv_bfloat16 h = __float2bfloat16_rn(v);
            thi[o] = h;
            tlo[o] = __float2bfloat16_rn(v - __bfloat162float(h));
        }
    }
}

// sincos LUT init (same fp32 numerics as before, hoisted)
__global__ __launch_bounds__(256) void sc_init(const float* __restrict__ inv_freq,
                                               float2* __restrict__ sc) {
    int i = blockIdx.x * 256 + threadIdx.x;
    int s = i >> 5, j = i & 31;
    float angle = (float)s * inv_freq[j];
    sc[i] = make_float2(sinf(angle), cosf(angle));
}

// RoPE + scale + bf16 hi/lo split, using LUT
__global__ __launch_bounds__(256) void rope_conv(const float* __restrict__ X,
                                                 __nv_bfloat16* __restrict__ hi,
                                                 __nv_bfloat16* __restrict__ lo,
                                                 const float2* __restrict__ sc,
                                                 int heads, float scale, int ld, int col0) {
    int idx = blockIdx.x * 8 + (threadIdx.x >> 5);
    int j = threadIdx.x & 31;
    int s = idx / heads;
    int h = idx - s * heads;
    const float* p = X + (size_t)s * ld + col0 + h * 64;
    float2 snc = sc[s * 32 + j];
    float a = p[j], b = p[32 + j];
    float r0 = (a * snc.y + b * snc.x) * scale;
    float r1 = (a * snc.x - b * snc.y) * scale;
    size_t o = (size_t)s * heads * 64 + h * 64;
    __nv_bfloat16 h0 = __float2bfloat16_rn(r0);
    __nv_bfloat16 h1 = __float2bfloat16_rn(r1);
    hi[o + j] = h0;
    hi[o + 32 + j] = h1;
    lo[o + j] = __float2bfloat16_rn(r0 - __bfloat162float(h0));
    lo[o + 32 + j] = __float2bfloat16_rn(r1 - __bfloat162float(h1));
}

// ---------------- bf16 3-pass GEMM (QKV projection) ----------------
#define TILE_B 10240
#define BUF_B  40960
#define G_SMEM (2 * BUF_B)

__device__ __forceinline__ void tile_async(uint32_t dst, const void* src_,
                                           int ldk, int tid) {
    const __nv_bfloat16* src = (const __nv_bfloat16*)src_;
#pragma unroll
    for (int t = 0; t < 2; t++) {
        int i = tid + t * 256;
        int r = i >> 2, q = i & 3;
        const void* g = src + (size_t)r * ldk + q * 8;
        CP_ASYNC16(dst + r * 80 + q * 16, g);
    }
}

__global__ __launch_bounds__(256, 1) void gemm_mma(
    const __nv_bfloat16* __restrict__ Ahi, const __nv_bfloat16* __restrict__ Alo,
    const __nv_bfloat16* __restrict__ Bhi, const __nv_bfloat16* __restrict__ Blo,
    float* __restrict__ C, int M, int N, int K) {
    extern __shared__ char smem[];
    const uint32_t sb = smem_u32(smem);
    const int tid = threadIdx.x;
    const int w = tid >> 5;
    const int lane = tid & 31;
    const int wm = (w & 1) * 64;
    const int wn = (w >> 1) * 32;
    const int m0 = blockIdx.y * 128;
    const int n0 = blockIdx.x * 128;

    const int a_row = lane & 15;
    const int a_kh = (lane >> 4) & 1;
    const int b_n = (lane & 7) + ((lane >> 4) << 3);
    const int b_kh = (lane >> 3) & 1;

    float acc[4][4][4];
#pragma unroll
    for (int i = 0; i < 4; i++)
#pragma unroll
        for (int j = 0; j < 4; j++)
#pragma unroll
            for (int r = 0; r < 4; r++) acc[i][j][r] = 0.f;

    const int NC = K >> 5;
    {
        const size_t ak = (size_t)m0 * K;
        const size_t bk = (size_t)n0 * K;
        tile_async(sb,              Ahi + ak, K, tid);
        tile_async(sb + TILE_B,     Alo + ak, K, tid);
        tile_async(sb + 2 * TILE_B, Bhi + bk, K, tid);
        tile_async(sb + 3 * TILE_B, Blo + bk, K, tid);
        CP_COMMIT();
    }

    for (int c = 0; c < NC; c++) {
        CP_WAIT0();
        __syncthreads();
        if (c + 1 < NC) {
            const uint32_t nb = sb + ((c + 1) & 1) * BUF_B;
            const size_t ak = (size_t)m0 * K + (size_t)(c + 1) * 32;
            const size_t bk = (size_t)n0 * K + (size_t)(c + 1) * 32;
            tile_async(nb,              Ahi + ak, K, tid);
            tile_async(nb + TILE_B,     Alo + ak, K, tid);
            tile_async(nb + 2 * TILE_B, Bhi + bk, K, tid);
            tile_async(nb + 3 * TILE_B, Blo + bk, K, tid);
            CP_COMMIT();
        }
        const uint32_t base = sb + (c & 1) * BUF_B;

#pragma unroll
        for (int ks = 0; ks < 32; ks += 16) {
            uint32_t ah[4][4], al[4][4], bh[2][4], bl[2][4];
            const uint32_t aoff = (uint32_t)((wm + a_row) * 80 + (ks + a_kh * 8) * 2);
            const uint32_t boff = (uint32_t)((wn + b_n) * 80 + (ks + b_kh * 8) * 2);
#pragma unroll
            for (int mt = 0; mt < 4; mt++) {
                LDSM4(ah[mt][0], ah[mt][1], ah[mt][2], ah[mt][3],
                      base + aoff + mt * 16 * 80);
                LDSM4(al[mt][0], al[mt][1], al[mt][2], al[mt][3],
                      base + TILE_B + aoff + mt * 16 * 80);
            }
#pragma unroll
            for (int np = 0; np < 2; np++) {
                LDSM4(bh[np][0], bh[np][1], bh[np][2], bh[np][3],
                      base + 2 * TILE_B + boff + np * 16 * 80);
                LDSM4(bl[np][0], bl[np][1], bl[np][2], bl[np][3],
                      base + 3 * TILE_B + boff + np * 16 * 80);
            }
#pragma unroll
            for (int mt = 0; mt < 4; mt++)
#pragma unroll
                for (int np = 0; np < 2; np++) {
                    MMA16816(acc[mt][np * 2 + 0], ah[mt], bh[np][0], bh[np][1]);
                    MMA16816(acc[mt][np * 2 + 1], ah[mt], bh[np][2], bh[np][3]);
                }
#pragma unroll
            for (int mt = 0; mt < 4; mt++)
#pragma unroll
                for (int np = 0; np < 2; np++) {
                    MMA16816(acc[mt][np * 2 + 0], ah[mt], bl[np][0], bl[np][1]);
                    MMA16816(acc[mt][np * 2 + 1], ah[mt], bl[np][2], bl[np][3]);
                }
#pragma unroll
            for (int mt = 0; mt < 4; mt++)
#pragma unroll
                for (int np = 0; np < 2; np++) {
                    MMA16816(acc[mt][np * 2 + 0], al[mt], bh[np][0], bh[np][1]);
                    MMA16816(acc[mt][np * 2 + 1], al[mt], bh[np][2], bh[np][3]);
                }
        }
    }

    const int g = lane >> 2, c2 = lane & 3;
#pragma unroll
    for (int mt = 0; mt < 4; mt++) {
        const int row = m0 + wm + mt * 16 + g;
#pragma unroll
        for (int nt = 0; nt < 4; nt++) {
            const int col = n0 + wn + nt * 8 + c2 * 2;
            *(float2*)&C[(size_t)row * N + col] =
                make_float2(acc[mt][nt][0], acc[mt][nt][1]);
            *(float2*)&C[(size_t)(row + 8) * N + col] =
                make_float2(acc[mt][nt][2], acc[mt][nt][3]);
        }
    }
}

// ---------------- fp16 2-pass GEMM (O projection): C = (Ah+Al) @ Bh^T ----------------
#define BUF2_B 30720
#define G2_SMEM (2 * BUF2_B)

__global__ __launch_bounds__(256, 1) void gemm_mma2(
    const __half* __restrict__ Ahi, const __half* __restrict__ Alo,
    const __half* __restrict__ Bh,
    float* __restrict__ C, int M, int N, int K) {
    extern __shared__ char smem[];
    const uint32_t sb = smem_u32(smem);
    const int tid = threadIdx.x;
    const int w = tid >> 5;
    const int lane = tid & 31;
    const int wm = (w & 1) * 64;
    const int wn = (w >> 1) * 32;
    const int m0 = blockIdx.y * 128;
    const int n0 = blockIdx.x * 128;

    const int a_row = lane & 15;
    const int a_kh = (lane >> 4) & 1;
    const int b_n = (lane & 7) + ((lane >> 4) << 3);
    const int b_kh = (lane >> 3) & 1;

    float acc[4][4][4];
#pragma unroll
    for (int i = 0; i < 4; i++)
#pragma unroll
        for (int j = 0; j < 4; j++)
#pragma unroll
            for (int r = 0; r < 4; r++) acc[i][j][r] = 0.f;

    const int NC = K >> 5;
    {
        const size_t ak = (size_t)m0 * K;
        const size_t bk = (size_t)n0 * K;
        tile_async(sb,              Ahi + ak, K, tid);
        tile_async(sb + TILE_B,     Alo + ak, K, tid);
        tile_async(sb + 2 * TILE_B, Bh + bk, K, tid);
        CP_COMMIT();
    }

    for (int c = 0; c < NC; c++) {
        CP_WAIT0();
        __syncthreads();
        if (c + 1 < NC) {
            const uint32_t nb = sb + ((c + 1) & 1) * BUF2_B;
            const size_t ak = (size_t)m0 * K + (size_t)(c + 1) * 32;
            const size_t bk = (size_t)n0 * K + (size_t)(c + 1) * 32;
            tile_async(nb,              Ahi + ak, K, tid);
            tile_async(nb + TILE_B,     Alo + ak, K, tid);
            tile_async(nb + 2 * TILE_B, Bh + bk, K, tid);
            CP_COMMIT();
        }
        const uint32_t base = sb + (c & 1) * BUF2_B;

#pragma unroll
        for (int ks = 0; ks < 32; ks += 16) {
            uint32_t ah[4][4], al[4][4], bh[2][4];
            const uint32_t aoff = (uint32_t)((wm + a_row) * 80 + (ks + a_kh * 8) * 2);
            const uint32_t boff = (uint32_t)((wn + b_n) * 80 + (ks + b_kh * 8) * 2);
#pragma unroll
            for (int mt = 0; mt < 4; mt++) {
                LDSM4(ah[mt][0], ah[mt][1], ah[mt][2], ah[mt][3],
                      base + aoff + mt * 16 * 80);
                LDSM4(al[mt][0], al[mt][1], al[mt][2], al[mt][3],
                      base + TILE_B + aoff + mt * 16 * 80);
            }
#pragma unroll
            for (int np = 0; np < 2; np++)
                LDSM4(bh[np][0], bh[np][1], bh[np][2], bh[np][3],
                      base + 2 * TILE_B + boff + np * 16 * 80);
#pragma unroll
            for (int mt = 0; mt < 4; mt++)
#pragma unroll
                for (int np = 0; np < 2; np++) {
                    MMA16816F(acc[mt][np * 2 + 0], ah[mt], bh[np][0], bh[np][1]);
                    MMA16816F(acc[mt][np * 2 + 1], ah[mt], bh[np][2], bh[np][3]);
                }
#pragma unroll
            for (int mt = 0; mt < 4; mt++)
#pragma unroll
                for (int np = 0; np < 2; np++) {
                    MMA16816F(acc[mt][np * 2 + 0], al[mt], bh[np][0], bh[np][1]);
                    MMA16816F(acc[mt][np * 2 + 1], al[mt], bh[np][2], bh[np][3]);
                }
        }
    }

    const int g = lane >> 2, c2 = lane & 3;
#pragma unroll
    for (int mt = 0; mt < 4; mt++) {
        const int row = m0 + wm + mt * 16 + g;
#pragma unroll
        for (int nt = 0; nt < 4; nt++) {
            const int col = n0 + wn + nt * 8 + c2 * 2;
            *(float2*)&C[(size_t)row * N + col] =
                make_float2(acc[mt][nt][0], acc[mt][nt][1]);
            *(float2*)&C[(size_t)(row + 8) * N + col] =
                make_float2(acc[mt][nt][2], acc[mt][nt][3]);
        }
    }
}

// ---------------- tensor-core flash attention ----------------
// smem: Qhi(0) Qlo(18432) | KV buffers: Khi(0) Klo(9216) Vh(18432), 27648 each
#define FQ_H 0
#define FQ_L 18432
#define FKV  36864
#define FKV_STRIDE 27648
#define F_SMEM 92160

__device__ __forceinline__ void pack_hl16(float p0, float p1, uint32_t& hi, uint32_t& lo) {
    __half2 h = __floats2half2_rn(p0, p1);
    hi = *reinterpret_cast<uint32_t*>(&h);
    __half2 l = __floats2half2_rn(p0 - __half2float(__low2half(h)),
                                  p1 - __half2float(__high2half(h)));
    lo = *reinterpret_cast<uint32_t*>(&l);
}

__global__ __launch_bounds__(256, 2) void flash_mma(
    const __nv_bfloat16* __restrict__ Qhi, const __nv_bfloat16* __restrict__ Qlo,
    const __nv_bfloat16* __restrict__ Khi, const __nv_bfloat16* __restrict__ Klo,
    const __half* __restrict__ Vh,
    __half* __restrict__ Ohf, __half* __restrict__ Olf) {
    extern __shared__ char smem[];
    const uint32_t sb = smem_u32(smem);
    const int tid = threadIdx.x;
    const int lane = tid & 31;
    const int w = tid >> 5;
    const int ib = gridDim.x - 1 - blockIdx.x;
    const int qh = blockIdx.y;
    const int kh = qh >> 2;
    const int qbase = ib * 128;

#pragma unroll
    for (int i = 0; i < 8; i++) {
        int idx = tid + i * 256;
        int sub = idx >> 10, r = (idx >> 3) & 127, q = idx & 7;
        const __nv_bfloat16* src = (sub ? Qlo : Qhi) + (size_t)(qbase + r) * HID + qh * 64 + q * 8;
        CP_ASYNC16(sb + sub * 18432 + r * 144 + q * 16, src);
    }
    CP_COMMIT();

    // KV chunk 0 -> buf 0 (3 sub-tiles: Khi, Klo, Vh)
#pragma unroll
    for (int i = 0; i < 6; i++) {
        int idx = tid + i * 256;
        int sub = idx >> 9, r = (idx >> 3) & 63, q = idx & 7;
        const uint16_t* base = (sub == 0) ? (const uint16_t*)Khi
                               : (sub == 1) ? (const uint16_t*)Klo : (const uint16_t*)Vh;
        const void* src = base + (size_t)r * KVD + kh * 64 + q * 8;
        CP_ASYNC16(sb + FKV + sub * 9216 + r * 144 + q * 16, src);
    }
    CP_COMMIT();

    const int a_row = lane & 15, a_kh = lane >> 4;
    const int b_n = (lane & 7) + ((lane >> 4) << 3), b_kh = (lane >> 3) & 1;
    const int v_k = (lane & 7) + ((lane >> 3) & 1) * 8, v_n = (lane >> 4) * 8;
    const int g = lane >> 2, tg = lane & 3;

    float o[8][4];
#pragma unroll
    for (int nt = 0; nt < 8; nt++)
#pragma unroll
        for (int r = 0; r < 4; r++) o[nt][r] = 0.f;
    float m0 = -1e30f, m1 = -1e30f, l0 = 0.f, l1 = 0.f;

    const int jbmax = 2 * ib + 1;
    for (int jb = 0; jb <= jbmax; jb++) {
        const uint32_t kvb = sb + FKV + (jb & 1) * FKV_STRIDE;
        __syncthreads();
        if (jb < jbmax) {
            const uint32_t nb = sb + FKV + ((jb + 1) & 1) * FKV_STRIDE;
#pragma unroll
            for (int i = 0; i < 6; i++) {
                int idx = tid + i * 256;
                int sub = idx >> 9, r = (idx >> 3) & 63, q = idx & 7;
                const uint16_t* base = (sub == 0) ? (const uint16_t*)Khi
                                       : (sub == 1) ? (const uint16_t*)Klo : (const uint16_t*)Vh;
                const void* src = base + (size_t)((jb + 1) * 64 + r) * KVD + kh * 64 + q * 8;
                CP_ASYNC16(nb + sub * 9216 + r * 144 + q * 16, src);
            }
            CP_COMMIT();
            CP_WAIT1();
        } else {
            CP_WAIT0();
        }
        __syncthreads();

        // S = Q K^T (bf16 3-pass, pass-major)
        float s[8][4];
#pragma unroll
        for (int nt = 0; nt < 8; nt++)
#pragma unroll
            for (int r = 0; r < 4; r++) s[nt][r] = 0.f;
#pragma unroll
        for (int kc = 0; kc < 4; kc++) {
            uint32_t ah[4], al[4];
            const uint32_t aoff = (w * 16 + a_row) * 144 + (kc * 16 + a_kh * 8) * 2;
            LDSM4(ah[0], ah[1], ah[2], ah[3], sb + FQ_H + aoff);
            LDSM4(al[0], al[1], al[2], al[3], sb + FQ_L + aoff);
#pragma unroll
            for (int n2p = 0; n2p < 2; n2p++) {
                uint32_t bh[2][4], bl[2][4];
#pragma unroll
                for (int j = 0; j < 2; j++) {
                    const int n2 = n2p * 2 + j;
                    const uint32_t boff = (n2 * 16 + b_n) * 144 + (kc * 16 + b_kh * 8) * 2;
                    LDSM4(bh[j][0], bh[j][1], bh[j][2], bh[j][3], kvb + boff);
                    LDSM4(bl[j][0], bl[j][1], bl[j][2], bl[j][3], kvb + 9216 + boff);
                }
#pragma unroll
                for (int j = 0; j < 2; j++) {
                    const int n2 = n2p * 2 + j;
                    MMA16816(s[n2 * 2 + 0], ah, bh[j][0], bh[j][1]);
                    MMA16816(s[n2 * 2 + 1], ah, bh[j][2], bh[j][3]);
                }
#pragma unroll
                for (int j = 0; j < 2; j++) {
                    const int n2 = n2p * 2 + j;
                    MMA16816(s[n2 * 2 + 0], ah, bl[j][0], bl[j][1]);
                    MMA16816(s[n2 * 2 + 1], ah, bl[j][2], bl[j][3]);
                }
#pragma unroll
                for (int j = 0; j < 2; j++) {
                    const int n2 = n2p * 2 + j;
                    MMA16816(s[n2 * 2 + 0], al, bh[j][0], bh[j][1]);
                    MMA16816(s[n2 * 2 + 1], al, bh[j][2], bh[j][3]);
                }
            }
        }

        if (jb >= 2 * ib) {
            const int row0 = qbase + w * 16 + g;
            const int row1 = row0 + 8;
#pragma unroll
            for (int nt = 0; nt < 8; nt++) {
                const int col = jb * 64 + nt * 8 + tg * 2;
                if (col > row0) s[nt][0] = -1e30f;
                if (col + 1 > row0) s[nt][1] = -1e30f;
                if (col > row1) s[nt][2] = -1e30f;
                if (col + 1 > row1) s[nt][3] = -1e30f;
            }
        }

        float mx0 = -1e30f, mx1 = -1e30f;
#pragma unroll
        for (int nt = 0; nt < 8; nt++) {
            mx0 = fmaxf(mx0, fmaxf(s[nt][0], s[nt][1]));
            mx1 = fmaxf(mx1, fmaxf(s[nt][2], s[nt][3]));
        }
        mx0 = fmaxf(mx0, __shfl_xor_sync(0xffffffff, mx0, 1));
        mx0 = fmaxf(mx0, __shfl_xor_sync(0xffffffff, mx0, 2));
        mx1 = fmaxf(mx1, __shfl_xor_sync(0xffffffff, mx1, 1));
        mx1 = fmaxf(mx1, __shfl_xor_sync(0xffffffff, mx1, 2));
        const float mn0 = fmaxf(m0, mx0), mn1 = fmaxf(m1, mx1);
        const float al0 = __expf(m0 - mn0), al1 = __expf(m1 - mn1);
        m0 = mn0; m1 = mn1;

        float rs0 = 0.f, rs1 = 0.f;
#pragma unroll
        for (int nt = 0; nt < 8; nt++) {
            s[nt][0] = __expf(s[nt][0] - mn0);
            s[nt][1] = __expf(s[nt][1] - mn0);
            s[nt][2] = __expf(s[nt][2] - mn1);
            s[nt][3] = __expf(s[nt][3] - mn1);
            rs0 += s[nt][0] + s[nt][1];
            rs1 += s[nt][2] + s[nt][3];
            o[nt][0] *= al0; o[nt][1] *= al0;
            o[nt][2] *= al1; o[nt][3] *= al1;
        }
        rs0 += __shfl_xor_sync(0xffffffff, rs0, 1);
        rs0 += __shfl_xor_sync(0xffffffff, rs0, 2);
        rs1 += __shfl_xor_sync(0xffffffff, rs1, 1);
        rs1 += __shfl_xor_sync(0xffffffff, rs1, 2);
        l0 = l0 * al0 + rs0;
        l1 = l1 * al1 + rs1;

        // O += P @ V : fp16 2-pass (P hi/lo fp16, V hi fp16)
#pragma unroll
        for (int kc2 = 0; kc2 < 4; kc2++) {
            uint32_t aph[4], apl[4];
            pack_hl16(s[2 * kc2][0], s[2 * kc2][1], aph[0], apl[0]);
            pack_hl16(s[2 * kc2][2], s[2 * kc2][3], aph[1], apl[1]);
            pack_hl16(s[2 * kc2 + 1][0], s[2 * kc2 + 1][1], aph[2], apl[2]);
            pack_hl16(s[2 * kc2 + 1][2], s[2 * kc2 + 1][3], aph[3], apl[3]);
#pragma unroll
            for (int n2p = 0; n2p < 2; n2p++) {
                uint32_t vh[2][4];
#pragma unroll
                for (int j = 0; j < 2; j++) {
                    const int n2 = n2p * 2 + j;
                    const uint32_t voff = (kc2 * 16 + v_k) * 144 + (n2 * 16 + v_n) * 2;
                    LDSM4T(vh[j][0], vh[j][1], vh[j][2], vh[j][3], kvb + 2 * 9216 + voff);
                }
#pragma unroll
                for (int j = 0; j < 2; j++) {
                    const int n2 = n2p * 2 + j;
                    MMA16816F(o[n2 * 2 + 0], aph, vh[j][0], vh[j][1]);
                    MMA16816F(o[n2 * 2 + 1], aph, vh[j][2], vh[j][3]);
                }
#pragma unroll
                for (int j = 0; j < 2; j++) {
                    const int n2 = n2p * 2 + j;
                    MMA16816F(o[n2 * 2 + 0], apl, vh[j][0], vh[j][1]);
                    MMA16816F(o[n2 * 2 + 1], apl, vh[j][2], vh[j][3]);
                }
            }
        }
    }

    // epilogue: write fp16 hi/lo (feeds fp16 2-pass o_proj GEMM)
    const float il0 = 1.0f / l0, il1 = 1.0f / l1;
    const int row0 = qbase + w * 16 + g;
#pragma unroll
    for (int nt = 0; nt < 8; nt++) {
        const int col = qh * 64 + nt * 8 + tg * 2;
        uint32_t h, l;
        pack_hl16(o[nt][0] * il0, o[nt][1] * il0, h, l);
        *(uint32_t*)&Ohf[(size_t)row0 * HID + col] = h;
        *(uint32_t*)&Olf[(size_t)row0 * HID + col] = l;
        pack_hl16(o[nt][2] * il1, o[nt][3] * il1, h, l);
        *(uint32_t*)&Ohf[(size_t)(row0 + 8) * HID + col] = h;
        *(uint32_t*)&Olf[(size_t)(row0 + 8) * HID + col] = l;
    }
}

// ---------------------------------------------------------------------------
extern "C" void kernel_launch(void* const* d_in, const int* in_sizes, int n_in,
                              void* d_out, int out_size) {
    const float* x        = (const float*)d_in[0];
    const float* q_proj   = (const float*)d_in[1];
    const float* k_proj   = (const float*)d_in[2];
    const float* v_proj   = (const float*)d_in[3];
    const float* o_proj   = (const float*)d_in[4];
    const float* inv_freq = (const float*)d_in[5];
    float* out = (float*)d_out;

    float *QKVb;
    __nv_bfloat16 *Ahi, *Alo, *Whi, *Wlo, *Khi, *Klo;
    __half *Ohf, *Olf, *Woh, *Vh;
    float2* sc;
    cudaGetSymbolAddress((void**)&QKVb, g_QKV);
    cudaGetSymbolAddress((void**)&Ahi, g_Ahi);
    cudaGetSymbolAddress((void**)&Alo, g_Alo);
    cudaGetSymbolAddress((void**)&Ohf, g_Ohf);
    cudaGetSymbolAddress((void**)&Olf, g_Olf);
    cudaGetSymbolAddress((void**)&Whi, g_Whi);
    cudaGetSymbolAddress((void**)&Wlo, g_Wlo);
    cudaGetSymbolAddress((void**)&Woh, g_Woh);
    cudaGetSymbolAddress((void**)&Khi, g_Khi);
    cudaGetSymbolAddress((void**)&Klo, g_Klo);
    cudaGetSymbolAddress((void**)&Vh, g_Vh);
    cudaGetSymbolAddress((void**)&sc, g_sc);

    cudaFuncSetAttribute(gemm_mma, cudaFuncAttributeMaxDynamicSharedMemorySize, G_SMEM);
    cudaFuncSetAttribute(gemm_mma2, cudaFuncAttributeMaxDynamicSharedMemorySize, G2_SMEM);
    cudaFuncSetAttribute(flash_mma, cudaFuncAttributeMaxDynamicSharedMemorySize, F_SMEM);

    const int convBlocks = (SEQ * HID / 4) / 256;

    convert_hl<<<convBlocks, 256>>>(x, Ahi, Alo);
    transpose_all<<<dim3(160, HID / 32), 256>>>(q_proj, k_proj, v_proj, o_proj, Whi, Wlo, Woh);
    sc_init<<<SEQ * 32 / 256, 256>>>(inv_freq, sc);

    // fused QKV projection (bf16 3-pass)
    gemm_mma<<<dim3(QKVN / 128, SEQ / 128), 256, G_SMEM>>>(Ahi, Alo, Whi, Wlo, QKVb,
                                                           SEQ, QKVN, HID);

    // RoPE + splits
    rope_conv<<<SEQ * NQH / 8, 256>>>(QKVb, Ahi, Alo, sc, NQH, 0.125f, QKVN, 0);
    rope_conv<<<SEQ * NKH / 8, 256>>>(QKVb, Khi, Klo, sc, NKH, 1.0f, QKVN, HID);
    convert_h16_strided<<<(SEQ * KVD / 4) / 256, 256>>>(QKVb, Vh, QKVN, HID + KVD, KVD);

    // flash attention (S bf16 3-pass, PV fp16 2-pass)
    flash_mma<<<dim3(SEQ / 128, NQH), 256, F_SMEM>>>(Ahi, Alo, Khi, Klo, Vh, Ohf, Olf);

    // out = O @ o_proj (fp16 2-pass)
    gemm_mma2<<<dim3(HID / 128, SEQ / 128), 256, G2_SMEM>>>(Ohf, Olf, Woh, out, SEQ, HID, HID);
}

// round 8
// speedup vs baseline: 4.0662x; 1.0988x over previous
#include <cuda_runtime.h>
#include <cuda_bf16.h>
#include <cuda_fp16.h>
#include <math.h>
#include <cstdint>

#define SEQ 2048
#define HID 2048
#define KVD 512
#define QKVN 3072
#define NQH 32
#define NKH 8

// ---------------- scratch (no allocations allowed) ----------------
__device__ float g_QKV[SEQ * QKVN];
__device__ __nv_bfloat16 g_Ahi[SEQ * HID];
__device__ __nv_bfloat16 g_Alo[SEQ * HID];
__device__ __half g_Ohf[SEQ * HID];
__device__ __half g_Olf[SEQ * HID];
__device__ __nv_bfloat16 g_Whi[QKVN * HID];   // transposed q|k|v weights [N,K] bf16
__device__ __nv_bfloat16 g_Wlo[QKVN * HID];
__device__ __half g_Woh[HID * HID];           // transposed o weights, fp16 hi only
__device__ __nv_bfloat16 g_Khi[SEQ * KVD];
__device__ __nv_bfloat16 g_Klo[SEQ * KVD];
__device__ __half g_Vh[SEQ * KVD];            // V fp16 hi only
__device__ float2 g_sc[SEQ * 32];             // sincos LUT

// ---------------- helpers ----------------
__device__ __forceinline__ uint32_t smem_u32(const void* p) {
    uint32_t a;
    asm("{ .reg .u64 t; cvta.to.shared.u64 t, %1; cvt.u32.u64 %0, t; }" : "=r"(a) : "l"(p));
    return a;
}

#define LDSM4(r0, r1, r2, r3, addr) \
    asm volatile("ldmatrix.sync.aligned.m8n8.x4.shared.b16 {%0,%1,%2,%3}, [%4];" \
        : "=r"(r0), "=r"(r1), "=r"(r2), "=r"(r3) : "r"(addr))

#define LDSM4T(r0, r1, r2, r3, addr) \
    asm volatile("ldmatrix.sync.aligned.m8n8.x4.trans.shared.b16 {%0,%1,%2,%3}, [%4];" \
        : "=r"(r0), "=r"(r1), "=r"(r2), "=r"(r3) : "r"(addr))

#define MMA16816(d, a, b0, b1) \
    asm volatile("mma.sync.aligned.m16n8k16.row.col.f32.bf16.bf16.f32 " \
        "{%0,%1,%2,%3},{%4,%5,%6,%7},{%8,%9},{%0,%1,%2,%3};" \
        : "+f"((d)[0]), "+f"((d)[1]), "+f"((d)[2]), "+f"((d)[3]) \
        : "r"((a)[0]), "r"((a)[1]), "r"((a)[2]), "r"((a)[3]), "r"(b0), "r"(b1))

#define MMA16816F(d, a, b0, b1) \
    asm volatile("mma.sync.aligned.m16n8k16.row.col.f32.f16.f16.f32 " \
        "{%0,%1,%2,%3},{%4,%5,%6,%7},{%8,%9},{%0,%1,%2,%3};" \
        : "+f"((d)[0]), "+f"((d)[1]), "+f"((d)[2]), "+f"((d)[3]) \
        : "r"((a)[0]), "r"((a)[1]), "r"((a)[2]), "r"((a)[3]), "r"(b0), "r"(b1))

#define CP_ASYNC16(dst, src) \
    asm volatile("cp.async.cg.shared.global [%0], [%1], 16;" :: "r"(dst), "l"(src))
#define CP_COMMIT() asm volatile("cp.async.commit_group;" ::: "memory")
#define CP_WAIT0()  asm volatile("cp.async.wait_group 0;" ::: "memory")
#define CP_WAIT1()  asm volatile("cp.async.wait_group 1;" ::: "memory")

// ---------------- elementwise kernels ----------------
__device__ __forceinline__ uint32_t pack_bf2(__nv_bfloat16 a, __nv_bfloat16 b) {
    __nv_bfloat162 t(a, b);
    return *reinterpret_cast<uint32_t*>(&t);
}

__global__ __launch_bounds__(256) void convert_hl(const float* __restrict__ X,
                                                  __nv_bfloat16* __restrict__ hi,
                                                  __nv_bfloat16* __restrict__ lo) {
    int i = blockIdx.x * 256 + threadIdx.x;
    float4 v = *(const float4*)(X + (size_t)i * 4);
    __nv_bfloat16 h0 = __float2bfloat16_rn(v.x), h1 = __float2bfloat16_rn(v.y);
    __nv_bfloat16 h2 = __float2bfloat16_rn(v.z), h3 = __float2bfloat16_rn(v.w);
    __nv_bfloat16 l0 = __float2bfloat16_rn(v.x - __bfloat162float(h0));
    __nv_bfloat16 l1 = __float2bfloat16_rn(v.y - __bfloat162float(h1));
    __nv_bfloat16 l2 = __float2bfloat16_rn(v.z - __bfloat162float(h2));
    __nv_bfloat16 l3 = __float2bfloat16_rn(v.w - __bfloat162float(h3));
    *(uint2*)(hi + (size_t)i * 4) = make_uint2(pack_bf2(h0, h1), pack_bf2(h2, h3));
    *(uint2*)(lo + (size_t)i * 4) = make_uint2(pack_bf2(l0, l1), pack_bf2(l2, l3));
}

// strided fp32 -> fp16 (hi only) for V
__global__ __launch_bounds__(256) void convert_h16_strided(const float* __restrict__ X,
                                                           __half* __restrict__ h,
                                                           int ld, int col0, int cols) {
    int i = blockIdx.x * 256 + threadIdx.x;
    int r = i / (cols / 4), q = i % (cols / 4);
    float4 v = *(const float4*)(X + (size_t)r * ld + col0 + q * 4);
    __half2 a = __floats2half2_rn(v.x, v.y);
    __half2 b = __floats2half2_rn(v.z, v.w);
    *(uint2*)(h + (size_t)r * cols + q * 4) =
        make_uint2(*reinterpret_cast<uint32_t*>(&a), *reinterpret_cast<uint32_t*>(&b));
}

// fused transpose: q,k,v -> bf16 hi/lo into Whi/Wlo; o -> fp16 hi into Woh
__global__ __launch_bounds__(256) void transpose_all(const float* __restrict__ Wq,
                                                     const float* __restrict__ Wk,
                                                     const float* __restrict__ Wv,
                                                     const float* __restrict__ Wo,
                                                     __nv_bfloat16* __restrict__ thi,
                                                     __nv_bfloat16* __restrict__ tlo,
                                                     __half* __restrict__ toh) {
    __shared__ float t[32][33];
    int bx = blockIdx.x;
    const float* W;
    int N, nblk, dstoff;
    bool is_o = false;
    if (bx < 64)       { W = Wq; N = HID; nblk = bx;      dstoff = 0; }
    else if (bx < 80)  { W = Wk; N = KVD; nblk = bx - 64; dstoff = HID; }
    else if (bx < 96)  { W = Wv; N = KVD; nblk = bx - 80; dstoff = HID + KVD; }
    else               { W = Wo; N = HID; nblk = bx - 96; dstoff = 0; is_o = true; }
    int tx = threadIdx.x & 31, ty = threadIdx.x >> 5;
    int k0 = blockIdx.y * 32, n0 = nblk * 32;
#pragma unroll
    for (int i = 0; i < 4; i++)
        t[ty + i * 8][tx] = W[(size_t)(k0 + ty + i * 8) * N + n0 + tx];
    __syncthreads();
#pragma unroll
    for (int i = 0; i < 4; i++) {
        float v = t[tx][ty + i * 8];
        size_t o = (size_t)(dstoff + n0 + ty + i * 8) * HID + k0 + tx;
        if (is_o) {
            toh[o] = __float2half_rn(v);
        } else {
            __nv_bfloat16 h = __float2bfloat16_rn(v);
            thi[o] = h;
            tlo[o] = __float2bfloat16_rn(v - __bfloat162float(h));
        }
    }
}

// sincos LUT init
__global__ __launch_bounds__(256) void sc_init(const float* __restrict__ inv_freq,
                                               float2* __restrict__ sc) {
    int i = blockIdx.x * 256 + threadIdx.x;
    int s = i >> 5, j = i & 31;
    float angle = (float)s * inv_freq[j];
    sc[i] = make_float2(sinf(angle), cosf(angle));
}

// RoPE + scale + bf16 hi/lo split, using LUT
__global__ __launch_bounds__(256) void rope_conv(const float* __restrict__ X,
                                                 __nv_bfloat16* __restrict__ hi,
                                                 __nv_bfloat16* __restrict__ lo,
                                                 const float2* __restrict__ sc,
                                                 int heads, float scale, int ld, int col0) {
    int idx = blockIdx.x * 8 + (threadIdx.x >> 5);
    int j = threadIdx.x & 31;
    int s = idx / heads;
    int h = idx - s * heads;
    const float* p = X + (size_t)s * ld + col0 + h * 64;
    float2 snc = sc[s * 32 + j];
    float a = p[j], b = p[32 + j];
    float r0 = (a * snc.y + b * snc.x) * scale;
    float r1 = (a * snc.x - b * snc.y) * scale;
    size_t o = (size_t)s * heads * 64 + h * 64;
    __nv_bfloat16 h0 = __float2bfloat16_rn(r0);
    __nv_bfloat16 h1 = __float2bfloat16_rn(r1);
    hi[o + j] = h0;
    hi[o + 32 + j] = h1;
    lo[o + j] = __float2bfloat16_rn(r0 - __bfloat162float(h0));
    lo[o + 32 + j] = __float2bfloat16_rn(r1 - __bfloat162float(h1));
}

// ---------------- bf16 3-pass GEMM (QKV projection), occ 2 ----------------
#define TILE_B 10240
#define BUF_B  40960
#define G_SMEM (2 * BUF_B)

__device__ __forceinline__ void tile_async(uint32_t dst, const void* src_,
                                           int ldk, int tid) {
    const __nv_bfloat16* src = (const __nv_bfloat16*)src_;
#pragma unroll
    for (int t = 0; t < 2; t++) {
        int i = tid + t * 256;
        int r = i >> 2, q = i & 3;
        const void* g = src + (size_t)r * ldk + q * 8;
        CP_ASYNC16(dst + r * 80 + q * 16, g);
    }
}

__global__ __launch_bounds__(256, 2) void gemm_mma(
    const __nv_bfloat16* __restrict__ Ahi, const __nv_bfloat16* __restrict__ Alo,
    const __nv_bfloat16* __restrict__ Bhi, const __nv_bfloat16* __restrict__ Blo,
    float* __restrict__ C, int M, int N, int K) {
    extern __shared__ char smem[];
    const uint32_t sb = smem_u32(smem);
    const int tid = threadIdx.x;
    const int w = tid >> 5;
    const int lane = tid & 31;
    const int wm = (w & 1) * 64;
    const int wn = (w >> 1) * 32;
    const int m0 = blockIdx.y * 128;
    const int n0 = blockIdx.x * 128;

    const int a_row = lane & 15;
    const int a_kh = (lane >> 4) & 1;
    const int b_n = (lane & 7) + ((lane >> 4) << 3);
    const int b_kh = (lane >> 3) & 1;

    float acc[4][4][4];
#pragma unroll
    for (int i = 0; i < 4; i++)
#pragma unroll
        for (int j = 0; j < 4; j++)
#pragma unroll
            for (int r = 0; r < 4; r++) acc[i][j][r] = 0.f;

    const int NC = K >> 5;
    {
        const size_t ak = (size_t)m0 * K;
        const size_t bk = (size_t)n0 * K;
        tile_async(sb,              Ahi + ak, K, tid);
        tile_async(sb + TILE_B,     Alo + ak, K, tid);
        tile_async(sb + 2 * TILE_B, Bhi + bk, K, tid);
        tile_async(sb + 3 * TILE_B, Blo + bk, K, tid);
        CP_COMMIT();
    }

    for (int c = 0; c < NC; c++) {
        CP_WAIT0();
        __syncthreads();
        if (c + 1 < NC) {
            const uint32_t nb = sb + ((c + 1) & 1) * BUF_B;
            const size_t ak = (size_t)m0 * K + (size_t)(c + 1) * 32;
            const size_t bk = (size_t)n0 * K + (size_t)(c + 1) * 32;
            tile_async(nb,              Ahi + ak, K, tid);
            tile_async(nb + TILE_B,     Alo + ak, K, tid);
            tile_async(nb + 2 * TILE_B, Bhi + bk, K, tid);
            tile_async(nb + 3 * TILE_B, Blo + bk, K, tid);
            CP_COMMIT();
        }
        const uint32_t base = sb + (c & 1) * BUF_B;

#pragma unroll
        for (int ks = 0; ks < 32; ks += 16) {
            uint32_t ah[4][4], al[4][4], bh[2][4], bl[2][4];
            const uint32_t aoff = (uint32_t)((wm + a_row) * 80 + (ks + a_kh * 8) * 2);
            const uint32_t boff = (uint32_t)((wn + b_n) * 80 + (ks + b_kh * 8) * 2);
#pragma unroll
            for (int mt = 0; mt < 4; mt++) {
                LDSM4(ah[mt][0], ah[mt][1], ah[mt][2], ah[mt][3],
                      base + aoff + mt * 16 * 80);
                LDSM4(al[mt][0], al[mt][1], al[mt][2], al[mt][3],
                      base + TILE_B + aoff + mt * 16 * 80);
            }
#pragma unroll
            for (int np = 0; np < 2; np++) {
                LDSM4(bh[np][0], bh[np][1], bh[np][2], bh[np][3],
                      base + 2 * TILE_B + boff + np * 16 * 80);
                LDSM4(bl[np][0], bl[np][1], bl[np][2], bl[np][3],
                      base + 3 * TILE_B + boff + np * 16 * 80);
            }
#pragma unroll
            for (int mt = 0; mt < 4; mt++)
#pragma unroll
                for (int np = 0; np < 2; np++) {
                    MMA16816(acc[mt][np * 2 + 0], ah[mt], bh[np][0], bh[np][1]);
                    MMA16816(acc[mt][np * 2 + 1], ah[mt], bh[np][2], bh[np][3]);
                }
#pragma unroll
            for (int mt = 0; mt < 4; mt++)
#pragma unroll
                for (int np = 0; np < 2; np++) {
                    MMA16816(acc[mt][np * 2 + 0], ah[mt], bl[np][0], bl[np][1]);
                    MMA16816(acc[mt][np * 2 + 1], ah[mt], bl[np][2], bl[np][3]);
                }
#pragma unroll
            for (int mt = 0; mt < 4; mt++)
#pragma unroll
                for (int np = 0; np < 2; np++) {
                    MMA16816(acc[mt][np * 2 + 0], al[mt], bh[np][0], bh[np][1]);
                    MMA16816(acc[mt][np * 2 + 1], al[mt], bh[np][2], bh[np][3]);
                }
        }
    }

    const int g = lane >> 2, c2 = lane & 3;
#pragma unroll
    for (int mt = 0; mt < 4; mt++) {
        const int row = m0 + wm + mt * 16 + g;
#pragma unroll
        for (int nt = 0; nt < 4; nt++) {
            const int col = n0 + wn + nt * 8 + c2 * 2;
            *(float2*)&C[(size_t)row * N + col] =
                make_float2(acc[mt][nt][0], acc[mt][nt][1]);
            *(float2*)&C[(size_t)(row + 8) * N + col] =
                make_float2(acc[mt][nt][2], acc[mt][nt][3]);
        }
    }
}

// ---------------- fp16 2-pass GEMM (O projection), occ 2 ----------------
#define BUF2_B 30720
#define G2_SMEM (2 * BUF2_B)

__global__ __launch_bounds__(256, 2) void gemm_mma2(
    const __half* __restrict__ Ahi, const __half* __restrict__ Alo,
    const __half* __restrict__ Bh,
    float* __restrict__ C, int M, int N, int K) {
    extern __shared__ char smem[];
    const uint32_t sb = smem_u32(smem);
    const int tid = threadIdx.x;
    const int w = tid >> 5;
    const int lane = tid & 31;
    const int wm = (w & 1) * 64;
    const int wn = (w >> 1) * 32;
    const int m0 = blockIdx.y * 128;
    const int n0 = blockIdx.x * 128;

    const int a_row = lane & 15;
    const int a_kh = (lane >> 4) & 1;
    const int b_n = (lane & 7) + ((lane >> 4) << 3);
    const int b_kh = (lane >> 3) & 1;

    float acc[4][4][4];
#pragma unroll
    for (int i = 0; i < 4; i++)
#pragma unroll
        for (int j = 0; j < 4; j++)
#pragma unroll
            for (int r = 0; r < 4; r++) acc[i][j][r] = 0.f;

    const int NC = K >> 5;
    {
        const size_t ak = (size_t)m0 * K;
        const size_t bk = (size_t)n0 * K;
        tile_async(sb,              Ahi + ak, K, tid);
        tile_async(sb + TILE_B,     Alo + ak, K, tid);
        tile_async(sb + 2 * TILE_B, Bh + bk, K, tid);
        CP_COMMIT();
    }

    for (int c = 0; c < NC; c++) {
        CP_WAIT0();
        __syncthreads();
        if (c + 1 < NC) {
            const uint32_t nb = sb + ((c + 1) & 1) * BUF2_B;
            const size_t ak = (size_t)m0 * K + (size_t)(c + 1) * 32;
            const size_t bk = (size_t)n0 * K + (size_t)(c + 1) * 32;
            tile_async(nb,              Ahi + ak, K, tid);
            tile_async(nb + TILE_B,     Alo + ak, K, tid);
            tile_async(nb + 2 * TILE_B, Bh + bk, K, tid);
            CP_COMMIT();
        }
        const uint32_t base = sb + (c & 1) * BUF2_B;

#pragma unroll
        for (int ks = 0; ks < 32; ks += 16) {
            uint32_t ah[4][4], al[4][4], bh[2][4];
            const uint32_t aoff = (uint32_t)((wm + a_row) * 80 + (ks + a_kh * 8) * 2);
            const uint32_t boff = (uint32_t)((wn + b_n) * 80 + (ks + b_kh * 8) * 2);
#pragma unroll
            for (int mt = 0; mt < 4; mt++) {
                LDSM4(ah[mt][0], ah[mt][1], ah[mt][2], ah[mt][3],
                      base + aoff + mt * 16 * 80);
                LDSM4(al[mt][0], al[mt][1], al[mt][2], al[mt][3],
                      base + TILE_B + aoff + mt * 16 * 80);
            }
#pragma unroll
            for (int np = 0; np < 2; np++)
                LDSM4(bh[np][0], bh[np][1], bh[np][2], bh[np][3],
                      base + 2 * TILE_B + boff + np * 16 * 80);
#pragma unroll
            for (int mt = 0; mt < 4; mt++)
#pragma unroll
                for (int np = 0; np < 2; np++) {
                    MMA16816F(acc[mt][np * 2 + 0], ah[mt], bh[np][0], bh[np][1]);
                    MMA16816F(acc[mt][np * 2 + 1], ah[mt], bh[np][2], bh[np][3]);
                }
#pragma unroll
            for (int mt = 0; mt < 4; mt++)
#pragma unroll
                for (int np = 0; np < 2; np++) {
                    MMA16816F(acc[mt][np * 2 + 0], al[mt], bh[np][0], bh[np][1]);
                    MMA16816F(acc[mt][np * 2 + 1], al[mt], bh[np][2], bh[np][3]);
                }
        }
    }

    const int g = lane >> 2, c2 = lane & 3;
#pragma unroll
    for (int mt = 0; mt < 4; mt++) {
        const int row = m0 + wm + mt * 16 + g;
#pragma unroll
        for (int nt = 0; nt < 4; nt++) {
            const int col = n0 + wn + nt * 8 + c2 * 2;
            *(float2*)&C[(size_t)row * N + col] =
                make_float2(acc[mt][nt][0], acc[mt][nt][1]);
            *(float2*)&C[(size_t)(row + 8) * N + col] =
                make_float2(acc[mt][nt][2], acc[mt][nt][3]);
        }
    }
}

// ---------------- tensor-core flash attention (unchanged) ----------------
#define FQ_H 0
#define FQ_L 18432
#define FKV  36864
#define FKV_STRIDE 27648
#define F_SMEM 92160

__device__ __forceinline__ void pack_hl16(float p0, float p1, uint32_t& hi, uint32_t& lo) {
    __half2 h = __floats2half2_rn(p0, p1);
    hi = *reinterpret_cast<uint32_t*>(&h);
    __half2 l = __floats2half2_rn(p0 - __half2float(__low2half(h)),
                                  p1 - __half2float(__high2half(h)));
    lo = *reinterpret_cast<uint32_t*>(&l);
}

__global__ __launch_bounds__(256, 2) void flash_mma(
    const __nv_bfloat16* __restrict__ Qhi, const __nv_bfloat16* __restrict__ Qlo,
    const __nv_bfloat16* __restrict__ Khi, const __nv_bfloat16* __restrict__ Klo,
    const __half* __restrict__ Vh,
    __half* __restrict__ Ohf, __half* __restrict__ Olf) {
    extern __shared__ char smem[];
    const uint32_t sb = smem_u32(smem);
    const int tid = threadIdx.x;
    const int lane = tid & 31;
    const int w = tid >> 5;
    const int ib = gridDim.x - 1 - blockIdx.x;
    const int qh = blockIdx.y;
    const int kh = qh >> 2;
    const int qbase = ib * 128;

#pragma unroll
    for (int i = 0; i < 8; i++) {
        int idx = tid + i * 256;
        int sub = idx >> 10, r = (idx >> 3) & 127, q = idx & 7;
        const __nv_bfloat16* src = (sub ? Qlo : Qhi) + (size_t)(qbase + r) * HID + qh * 64 + q * 8;
        CP_ASYNC16(sb + sub * 18432 + r * 144 + q * 16, src);
    }
    CP_COMMIT();

#pragma unroll
    for (int i = 0; i < 6; i++) {
        int idx = tid + i * 256;
        int sub = idx >> 9, r = (idx >> 3) & 63, q = idx & 7;
        const uint16_t* base = (sub == 0) ? (const uint16_t*)Khi
                               : (sub == 1) ? (const uint16_t*)Klo : (const uint16_t*)Vh;
        const void* src = base + (size_t)r * KVD + kh * 64 + q * 8;
        CP_ASYNC16(sb + FKV + sub * 9216 + r * 144 + q * 16, src);
    }
    CP_COMMIT();

    const int a_row = lane & 15, a_kh = lane >> 4;
    const int b_n = (lane & 7) + ((lane >> 4) << 3), b_kh = (lane >> 3) & 1;
    const int v_k = (lane & 7) + ((lane >> 3) & 1) * 8, v_n = (lane >> 4) * 8;
    const int g = lane >> 2, tg = lane & 3;

    float o[8][4];
#pragma unroll
    for (int nt = 0; nt < 8; nt++)
#pragma unroll
        for (int r = 0; r < 4; r++) o[nt][r] = 0.f;
    float m0 = -1e30f, m1 = -1e30f, l0 = 0.f, l1 = 0.f;

    const int jbmax = 2 * ib + 1;
    for (int jb = 0; jb <= jbmax; jb++) {
        const uint32_t kvb = sb + FKV + (jb & 1) * FKV_STRIDE;
        __syncthreads();
        if (jb < jbmax) {
            const uint32_t nb = sb + FKV + ((jb + 1) & 1) * FKV_STRIDE;
#pragma unroll
            for (int i = 0; i < 6; i++) {
                int idx = tid + i * 256;
                int sub = idx >> 9, r = (idx >> 3) & 63, q = idx & 7;
                const uint16_t* base = (sub == 0) ? (const uint16_t*)Khi
                                       : (sub == 1) ? (const uint16_t*)Klo : (const uint16_t*)Vh;
                const void* src = base + (size_t)((jb + 1) * 64 + r) * KVD + kh * 64 + q * 8;
                CP_ASYNC16(nb + sub * 9216 + r * 144 + q * 16, src);
            }
            CP_COMMIT();
            CP_WAIT1();
        } else {
            CP_WAIT0();
        }
        __syncthreads();

        // S = Q K^T (bf16 3-pass, pass-major)
        float s[8][4];
#pragma unroll
        for (int nt = 0; nt < 8; nt++)
#pragma unroll
            for (int r = 0; r < 4; r++) s[nt][r] = 0.f;
#pragma unroll
        for (int kc = 0; kc < 4; kc++) {
            uint32_t ah[4], al[4];
            const uint32_t aoff = (w * 16 + a_row) * 144 + (kc * 16 + a_kh * 8) * 2;
            LDSM4(ah[0], ah[1], ah[2], ah[3], sb + FQ_H + aoff);
            LDSM4(al[0], al[1], al[2], al[3], sb + FQ_L + aoff);
#pragma unroll
            for (int n2p = 0; n2p < 2; n2p++) {
                uint32_t bh[2][4], bl[2][4];
#pragma unroll
                for (int j = 0; j < 2; j++) {
                    const int n2 = n2p * 2 + j;
                    const uint32_t boff = (n2 * 16 + b_n) * 144 + (kc * 16 + b_kh * 8) * 2;
                    LDSM4(bh[j][0], bh[j][1], bh[j][2], bh[j][3], kvb + boff);
                    LDSM4(bl[j][0], bl[j][1], bl[j][2], bl[j][3], kvb + 9216 + boff);
                }
#pragma unroll
                for (int j = 0; j < 2; j++) {
                    const int n2 = n2p * 2 + j;
                    MMA16816(s[n2 * 2 + 0], ah, bh[j][0], bh[j][1]);
                    MMA16816(s[n2 * 2 + 1], ah, bh[j][2], bh[j][3]);
                }
#pragma unroll
                for (int j = 0; j < 2; j++) {
                    const int n2 = n2p * 2 + j;
                    MMA16816(s[n2 * 2 + 0], ah, bl[j][0], bl[j][1]);
                    MMA16816(s[n2 * 2 + 1], ah, bl[j][2], bl[j][3]);
                }
#pragma unroll
                for (int j = 0; j < 2; j++) {
                    const int n2 = n2p * 2 + j;
                    MMA16816(s[n2 * 2 + 0], al, bh[j][0], bh[j][1]);
                    MMA16816(s[n2 * 2 + 1], al, bh[j][2], bh[j][3]);
                }
            }
        }

        if (jb >= 2 * ib) {
            const int row0 = qbase + w * 16 + g;
            const int row1 = row0 + 8;
#pragma unroll
            for (int nt = 0; nt < 8; nt++) {
                const int col = jb * 64 + nt * 8 + tg * 2;
                if (col > row0) s[nt][0] = -1e30f;
                if (col + 1 > row0) s[nt][1] = -1e30f;
                if (col > row1) s[nt][2] = -1e30f;
                if (col + 1 > row1) s[nt][3] = -1e30f;
            }
        }

        float mx0 = -1e30f, mx1 = -1e30f;
#pragma unroll
        for (int nt = 0; nt < 8; nt++) {
            mx0 = fmaxf(mx0, fmaxf(s[nt][0], s[nt][1]));
            mx1 = fmaxf(mx1, fmaxf(s[nt][2], s[nt][3]));
        }
        mx0 = fmaxf(mx0, __shfl_xor_sync(0xffffffff, mx0, 1));
        mx0 = fmaxf(mx0, __shfl_xor_sync(0xffffffff, mx0, 2));
        mx1 = fmaxf(mx1, __shfl_xor_sync(0xffffffff, mx1, 1));
        mx1 = fmaxf(mx1, __shfl_xor_sync(0xffffffff, mx1, 2));
        const float mn0 = fmaxf(m0, mx0), mn1 = fmaxf(m1, mx1);
        const float al0 = __expf(m0 - mn0), al1 = __expf(m1 - mn1);
        m0 = mn0; m1 = mn1;

        float rs0 = 0.f, rs1 = 0.f;
#pragma unroll
        for (int nt = 0; nt < 8; nt++) {
            s[nt][0] = __expf(s[nt][0] - mn0);
            s[nt][1] = __expf(s[nt][1] - mn0);
            s[nt][2] = __expf(s[nt][2] - mn1);
            s[nt][3] = __expf(s[nt][3] - mn1);
            rs0 += s[nt][0] + s[nt][1];
            rs1 += s[nt][2] + s[nt][3];
            o[nt][0] *= al0; o[nt][1] *= al0;
            o[nt][2] *= al1; o[nt][3] *= al1;
        }
        rs0 += __shfl_xor_sync(0xffffffff, rs0, 1);
        rs0 += __shfl_xor_sync(0xffffffff, rs0, 2);
        rs1 += __shfl_xor_sync(0xffffffff, rs1, 1);
        rs1 += __shfl_xor_sync(0xffffffff, rs1, 2);
        l0 = l0 * al0 + rs0;
        l1 = l1 * al1 + rs1;

        // O += P @ V : fp16 2-pass
#pragma unroll
        for (int kc2 = 0; kc2 < 4; kc2++) {
            uint32_t aph[4], apl[4];
            pack_hl16(s[2 * kc2][0], s[2 * kc2][1], aph[0], apl[0]);
            pack_hl16(s[2 * kc2][2], s[2 * kc2][3], aph[1], apl[1]);
            pack_hl16(s[2 * kc2 + 1][0], s[2 * kc2 + 1][1], aph[2], apl[2]);
            pack_hl16(s[2 * kc2 + 1][2], s[2 * kc2 + 1][3], aph[3], apl[3]);
#pragma unroll
            for (int n2p = 0; n2p < 2; n2p++) {
                uint32_t vh[2][4];
#pragma unroll
                for (int j = 0; j < 2; j++) {
                    const int n2 = n2p * 2 + j;
                    const uint32_t voff = (kc2 * 16 + v_k) * 144 + (n2 * 16 + v_n) * 2;
                    LDSM4T(vh[j][0], vh[j][1], vh[j][2], vh[j][3], kvb + 2 * 9216 + voff);
                }
#pragma unroll
                for (int j = 0; j < 2; j++) {
                    const int n2 = n2p * 2 + j;
                    MMA16816F(o[n2 * 2 + 0], aph, vh[j][0], vh[j][1]);
                    MMA16816F(o[n2 * 2 + 1], aph, vh[j][2], vh[j][3]);
                }
#pragma unroll
                for (int j = 0; j < 2; j++) {
                    const int n2 = n2p * 2 + j;
                    MMA16816F(o[n2 * 2 + 0], apl, vh[j][0], vh[j][1]);
                    MMA16816F(o[n2 * 2 + 1], apl, vh[j][2], vh[j][3]);
                }
            }
        }
    }

    const float il0 = 1.0f / l0, il1 = 1.0f / l1;
    const int row0 = qbase + w * 16 + g;
#pragma unroll
    for (int nt = 0; nt < 8; nt++) {
        const int col = qh * 64 + nt * 8 + tg * 2;
        uint32_t h, l;
        pack_hl16(o[nt][0] * il0, o[nt][1] * il0, h, l);
        *(uint32_t*)&Ohf[(size_t)row0 * HID + col] = h;
        *(uint32_t*)&Olf[(size_t)row0 * HID + col] = l;
        pack_hl16(o[nt][2] * il1, o[nt][3] * il1, h, l);
        *(uint32_t*)&Ohf[(size_t)(row0 + 8) * HID + col] = h;
        *(uint32_t*)&Olf[(size_t)(row0 + 8) * HID + col] = l;
    }
}

// ---------------------------------------------------------------------------
extern "C" void kernel_launch(void* const* d_in, const int* in_sizes, int n_in,
                              void* d_out, int out_size) {
    const float* x        = (const float*)d_in[0];
    const float* q_proj   = (const float*)d_in[1];
    const float* k_proj   = (const float*)d_in[2];
    const float* v_proj   = (const float*)d_in[3];
    const float* o_proj   = (const float*)d_in[4];
    const float* inv_freq = (const float*)d_in[5];
    float* out = (float*)d_out;

    float *QKVb;
    __nv_bfloat16 *Ahi, *Alo, *Whi, *Wlo, *Khi, *Klo;
    __half *Ohf, *Olf, *Woh, *Vh;
    float2* sc;
    cudaGetSymbolAddress((void**)&QKVb, g_QKV);
    cudaGetSymbolAddress((void**)&Ahi, g_Ahi);
    cudaGetSymbolAddress((void**)&Alo, g_Alo);
    cudaGetSymbolAddress((void**)&Ohf, g_Ohf);
    cudaGetSymbolAddress((void**)&Olf, g_Olf);
    cudaGetSymbolAddress((void**)&Whi, g_Whi);
    cudaGetSymbolAddress((void**)&Wlo, g_Wlo);
    cudaGetSymbolAddress((void**)&Woh, g_Woh);
    cudaGetSymbolAddress((void**)&Khi, g_Khi);
    cudaGetSymbolAddress((void**)&Klo, g_Klo);
    cudaGetSymbolAddress((void**)&Vh, g_Vh);
    cudaGetSymbolAddress((void**)&sc, g_sc);

    cudaFuncSetAttribute(gemm_mma, cudaFuncAttributeMaxDynamicSharedMemorySize, G_SMEM);
    cudaFuncSetAttribute(gemm_mma2, cudaFuncAttributeMaxDynamicSharedMemorySize, G2_SMEM);
    cudaFuncSetAttribute(flash_mma, cudaFuncAttributeMaxDynamicSharedMemorySize, F_SMEM);

    const int convBlocks = (SEQ * HID / 4) / 256;

    convert_hl<<<convBlocks, 256>>>(x, Ahi, Alo);
    transpose_all<<<dim3(160, HID / 32), 256>>>(q_proj, k_proj, v_proj, o_proj, Whi, Wlo, Woh);
    sc_init<<<SEQ * 32 / 256, 256>>>(inv_freq, sc);

    // fused QKV projection (bf16 3-pass)
    gemm_mma<<<dim3(QKVN / 128, SEQ / 128), 256, G_SMEM>>>(Ahi, Alo, Whi, Wlo, QKVb,
                                                           SEQ, QKVN, HID);

    // RoPE + splits
    rope_conv<<<SEQ * NQH / 8, 256>>>(QKVb, Ahi, Alo, sc, NQH, 0.125f, QKVN, 0);
    rope_conv<<<SEQ * NKH / 8, 256>>>(QKVb, Khi, Klo, sc, NKH, 1.0f, QKVN, HID);
    convert_h16_strided<<<(SEQ * KVD / 4) / 256, 256>>>(QKVb, Vh, QKVN, HID + KVD, KVD);

    // flash attention (S bf16 3-pass, PV fp16 2-pass)
    flash_mma<<<dim3(SEQ / 128, NQH), 256, F_SMEM>>>(Ahi, Alo, Khi, Klo, Vh, Ohf, Olf);

    // out = O @ o_proj (fp16 2-pass)
    gemm_mma2<<<dim3(HID / 128, SEQ / 128), 256, G2_SMEM>>>(Ohf, Olf, Woh, out, SEQ, HID, HID);
}